// round 1
// baseline (speedup 1.0000x reference)
#include <cuda_runtime.h>
#include <cstddef>

// Problem constants
#define B_TOT   16384
#define T_STEPS 128
#define F_IN    12
#define H1      64
#define H2      128
#define G0      256   // 4*H1
#define G1      512   // 4*H2
#define BT      64    // batch tile per block
#define NTHREADS 256

// ---------------------------------------------------------------------------
// Transposed weight scratch (device globals -> no allocation needed).
// Layout: Wt[k][j] so the inner product loop over k reads contiguous j,
// enabling float4 loads per gate group.
// ---------------------------------------------------------------------------
__device__ float g_Wt0x[F_IN * G0];
__device__ float g_Wt0h[H1 * G0];
__device__ float g_Wt1a[H1 * G1];
__device__ float g_Wt1h[H2 * G1];
__device__ float g_b0[G0];
__device__ float g_b1[G1];

__global__ void repack_kernel(const float* __restrict__ W_ih0, const float* __restrict__ W_hh0,
                              const float* __restrict__ b_ih0, const float* __restrict__ b_hh0,
                              const float* __restrict__ W_ih1, const float* __restrict__ W_hh1,
                              const float* __restrict__ b_ih1, const float* __restrict__ b_hh1)
{
    int tid = blockIdx.x * blockDim.x + threadIdx.x;
    int stride = gridDim.x * blockDim.x;
    for (int idx = tid; idx < F_IN * G0; idx += stride) {
        int k = idx / G0, j = idx % G0;
        g_Wt0x[idx] = W_ih0[j * F_IN + k];
    }
    for (int idx = tid; idx < H1 * G0; idx += stride) {
        int k = idx / G0, j = idx % G0;
        g_Wt0h[idx] = W_hh0[j * H1 + k];
    }
    for (int idx = tid; idx < H1 * G1; idx += stride) {
        int k = idx / G1, j = idx % G1;
        g_Wt1a[idx] = W_ih1[j * H1 + k];
    }
    for (int idx = tid; idx < H2 * G1; idx += stride) {
        int k = idx / G1, j = idx % G1;
        g_Wt1h[idx] = W_hh1[j * H2 + k];
    }
    for (int idx = tid; idx < G0; idx += stride) g_b0[idx] = b_ih0[idx] + b_hh0[idx];
    for (int idx = tid; idx < G1; idx += stride) g_b1[idx] = b_ih1[idx] + b_hh1[idx];
}

// Fast activations: MUFU.EX2 + MUFU.RCP based; rel err ~1e-6 << 1e-3 tolerance.
__device__ __forceinline__ float sigm(float x) {
    return __fdividef(1.0f, 1.0f + __expf(-x));
}
__device__ __forceinline__ float tanh_f(float x) {
    // tanh(x) = 1 - 2/(1+exp(2x))
    return 1.0f - __fdividef(2.0f, 1.0f + __expf(2.0f * x));
}

// ---------------------------------------------------------------------------
// Main persistent kernel: one block = 64 batch elements for all 128 steps.
// Thread mapping: eg = tid>>4 owns elements e0..e0+3; ng = tid&15 owns
// hidden-unit columns jcol0..jcol0+3 (contiguous -> float4 weight loads).
// Each thread keeps its cell states c in registers across all timesteps.
// ---------------------------------------------------------------------------
__global__ __launch_bounds__(NTHREADS) void lstm_kernel(
    const float* __restrict__ xin,
    const float* __restrict__ Wd1, const float* __restrict__ bd1,
    const float* __restrict__ Wd2, const float* __restrict__ bd2,
    float* __restrict__ out)
{
    extern __shared__ float sm[];
    float* sx  = sm;                     // BT * 13   (x_t staging, padded)
    float* sh0 = sx + BT * 13;           // BT * 65   (h0, padded)
    float* sh1 = sh0 + BT * 65;          // 2 * BT * 129 (h1 double buffer, padded)
    float* red = sh1 + 2 * BT * 129;     // NTHREADS  (dense reduction)

    const int tid = threadIdx.x;
    const int eg = tid >> 4;       // 0..15 -> element group
    const int ng = tid & 15;       // 0..15 -> unit group
    const int e0 = eg * 4;         // local element base
    const int ebase = blockIdx.x * BT;
    const int jcol0 = ng * 4;      // unit column base (within H-sized gate block)

    // Persistent cell states in registers
    float c0r[4][4];   // [elem][unit]
    float c1r[4][8];   // [elem][pass*4 + unit]
    #pragma unroll
    for (int e = 0; e < 4; e++) {
        #pragma unroll
        for (int u = 0; u < 4; u++) c0r[e][u] = 0.0f;
        #pragma unroll
        for (int u = 0; u < 8; u++) c1r[e][u] = 0.0f;
    }

    for (int i = tid; i < BT * 65; i += NTHREADS) sh0[i] = 0.0f;
    for (int i = tid; i < 2 * BT * 129; i += NTHREADS) sh1[i] = 0.0f;
    __syncthreads();

    int buf = 0;
    for (int t = 0; t < T_STEPS; t++) {
        // ---- stage x_t (768 floats = 3 per thread) ----
        #pragma unroll
        for (int i = 0; i < 3; i++) {
            int idx = tid + i * NTHREADS;
            int e = idx / F_IN, f = idx - e * F_IN;
            sx[e * 13 + f] = xin[((size_t)(ebase + e) * T_STEPS + t) * F_IN + f];
        }

        // ================= Layer 0 =================
        float acc[4][16];   // [elem][gate*4 + unit]
        #pragma unroll
        for (int g = 0; g < 4; g++) {
            #pragma unroll
            for (int u = 0; u < 4; u++) {
                float b = g_b0[g * H1 + jcol0 + u];
                #pragma unroll
                for (int e = 0; e < 4; e++) acc[e][g * 4 + u] = b;
            }
        }
        // hh part (reads OLD h0) — before the barrier
        #pragma unroll 2
        for (int k = 0; k < H1; k++) {
            float4 w[4];
            #pragma unroll
            for (int g = 0; g < 4; g++)
                w[g] = *(const float4*)&g_Wt0h[k * G0 + g * H1 + jcol0];
            #pragma unroll
            for (int e = 0; e < 4; e++) {
                float hv = sh0[(e0 + e) * 65 + k];
                #pragma unroll
                for (int g = 0; g < 4; g++) {
                    acc[e][g * 4 + 0] = fmaf(w[g].x, hv, acc[e][g * 4 + 0]);
                    acc[e][g * 4 + 1] = fmaf(w[g].y, hv, acc[e][g * 4 + 1]);
                    acc[e][g * 4 + 2] = fmaf(w[g].z, hv, acc[e][g * 4 + 2]);
                    acc[e][g * 4 + 3] = fmaf(w[g].w, hv, acc[e][g * 4 + 3]);
                }
            }
        }
        __syncthreads();   // x_t visible; all threads done reading old h0
        // ih part (reads x_t)
        #pragma unroll 2
        for (int k = 0; k < F_IN; k++) {
            float4 w[4];
            #pragma unroll
            for (int g = 0; g < 4; g++)
                w[g] = *(const float4*)&g_Wt0x[k * G0 + g * H1 + jcol0];
            #pragma unroll
            for (int e = 0; e < 4; e++) {
                float xv = sx[(e0 + e) * 13 + k];
                #pragma unroll
                for (int g = 0; g < 4; g++) {
                    acc[e][g * 4 + 0] = fmaf(w[g].x, xv, acc[e][g * 4 + 0]);
                    acc[e][g * 4 + 1] = fmaf(w[g].y, xv, acc[e][g * 4 + 1]);
                    acc[e][g * 4 + 2] = fmaf(w[g].z, xv, acc[e][g * 4 + 2]);
                    acc[e][g * 4 + 3] = fmaf(w[g].w, xv, acc[e][g * 4 + 3]);
                }
            }
        }
        // elementwise update; write new h0 (safe: old h0 reads done at barrier)
        #pragma unroll
        for (int e = 0; e < 4; e++) {
            #pragma unroll
            for (int u = 0; u < 4; u++) {
                float ig = sigm(acc[e][0 * 4 + u]);
                float fg = sigm(acc[e][1 * 4 + u]);
                float gg = tanh_f(acc[e][2 * 4 + u]);
                float og = sigm(acc[e][3 * 4 + u]);
                float c = fmaf(fg, c0r[e][u], ig * gg);
                c0r[e][u] = c;
                sh0[(e0 + e) * 65 + jcol0 + u] = og * tanh_f(c);
            }
        }
        __syncthreads();   // new h0 visible

        // ================= Layer 1 (two 64-unit passes) =================
        const float* h1old = sh1 + buf * BT * 129;
        float* h1new = sh1 + (buf ^ 1) * BT * 129;
        #pragma unroll 1
        for (int p = 0; p < 2; p++) {
            float a1[4][16];
            #pragma unroll
            for (int g = 0; g < 4; g++) {
                #pragma unroll
                for (int u = 0; u < 4; u++) {
                    float b = g_b1[g * H2 + p * 64 + jcol0 + u];
                    #pragma unroll
                    for (int e = 0; e < 4; e++) a1[e][g * 4 + u] = b;
                }
            }
            // input = new h0
            #pragma unroll 2
            for (int k = 0; k < H1; k++) {
                float4 w[4];
                #pragma unroll
                for (int g = 0; g < 4; g++)
                    w[g] = *(const float4*)&g_Wt1a[k * G1 + g * H2 + p * 64 + jcol0];
                #pragma unroll
                for (int e = 0; e < 4; e++) {
                    float hv = sh0[(e0 + e) * 65 + k];
                    #pragma unroll
                    for (int g = 0; g < 4; g++) {
                        a1[e][g * 4 + 0] = fmaf(w[g].x, hv, a1[e][g * 4 + 0]);
                        a1[e][g * 4 + 1] = fmaf(w[g].y, hv, a1[e][g * 4 + 1]);
                        a1[e][g * 4 + 2] = fmaf(w[g].z, hv, a1[e][g * 4 + 2]);
                        a1[e][g * 4 + 3] = fmaf(w[g].w, hv, a1[e][g * 4 + 3]);
                    }
                }
            }
            // recurrent = old h1
            #pragma unroll 2
            for (int k = 0; k < H2; k++) {
                float4 w[4];
                #pragma unroll
                for (int g = 0; g < 4; g++)
                    w[g] = *(const float4*)&g_Wt1h[k * G1 + g * H2 + p * 64 + jcol0];
                #pragma unroll
                for (int e = 0; e < 4; e++) {
                    float hv = h1old[(e0 + e) * 129 + k];
                    #pragma unroll
                    for (int g = 0; g < 4; g++) {
                        a1[e][g * 4 + 0] = fmaf(w[g].x, hv, a1[e][g * 4 + 0]);
                        a1[e][g * 4 + 1] = fmaf(w[g].y, hv, a1[e][g * 4 + 1]);
                        a1[e][g * 4 + 2] = fmaf(w[g].z, hv, a1[e][g * 4 + 2]);
                        a1[e][g * 4 + 3] = fmaf(w[g].w, hv, a1[e][g * 4 + 3]);
                    }
                }
            }
            // update; write to the OTHER buffer (no barrier needed between passes)
            #pragma unroll
            for (int e = 0; e < 4; e++) {
                #pragma unroll
                for (int u = 0; u < 4; u++) {
                    float ig = sigm(a1[e][0 * 4 + u]);
                    float fg = sigm(a1[e][1 * 4 + u]);
                    float gg = tanh_f(a1[e][2 * 4 + u]);
                    float og = sigm(a1[e][3 * 4 + u]);
                    float c = fmaf(fg, c1r[e][p * 4 + u], ig * gg);
                    c1r[e][p * 4 + u] = c;
                    h1new[(e0 + e) * 129 + p * 64 + jcol0 + u] = og * tanh_f(c);
                }
            }
        }
        buf ^= 1;
        __syncthreads();   // new h1 visible for next step
    }

    // ================= Final dense head =================
    // pred[e] = sum_m Wd2[m] * (dot(Wd1[m,:], h1[e,:]) + bd1[m]) + bd2
    const float* h1f = sh1 + buf * BT * 129;
    {
        int e = tid >> 2;      // 0..63
        int q = tid & 3;       // quarter of the 64 m-values
        float s = 0.0f;
        for (int m = q * 16; m < q * 16 + 16; m++) {
            float d = bd1[m];
            #pragma unroll 4
            for (int j = 0; j < H2; j++)
                d = fmaf(Wd1[m * H2 + j], h1f[e * 129 + j], d);
            s = fmaf(Wd2[m], d, s);
        }
        red[tid] = s;
        __syncthreads();
        if (q == 0)
            out[ebase + e] = red[tid] + red[tid + 1] + red[tid + 2] + red[tid + 3] + bd2[0];
    }
}

// ---------------------------------------------------------------------------
// Launch
// ---------------------------------------------------------------------------
extern "C" void kernel_launch(void* const* d_in, const int* in_sizes, int n_in,
                              void* d_out, int out_size)
{
    (void)in_sizes; (void)n_in; (void)out_size;
    const float* input_seq = (const float*)d_in[0];
    const float* W_ih0 = (const float*)d_in[1];
    const float* W_hh0 = (const float*)d_in[2];
    const float* b_ih0 = (const float*)d_in[3];
    const float* b_hh0 = (const float*)d_in[4];
    const float* W_ih1 = (const float*)d_in[5];
    const float* W_hh1 = (const float*)d_in[6];
    const float* b_ih1 = (const float*)d_in[7];
    const float* b_hh1 = (const float*)d_in[8];
    const float* W_d1  = (const float*)d_in[9];
    const float* b_d1  = (const float*)d_in[10];
    const float* W_d2  = (const float*)d_in[11];
    const float* b_d2  = (const float*)d_in[12];

    const int smem_bytes = (BT * 13 + BT * 65 + 2 * BT * 129 + NTHREADS) * sizeof(float); // 87040
    cudaFuncSetAttribute(lstm_kernel, cudaFuncAttributeMaxDynamicSharedMemorySize, smem_bytes);

    repack_kernel<<<64, 256>>>(W_ih0, W_hh0, b_ih0, b_hh0, W_ih1, W_hh1, b_ih1, b_hh1);
    lstm_kernel<<<B_TOT / BT, NTHREADS, smem_bytes>>>(
        input_seq, W_d1, b_d1, W_d2, b_d2, (float*)d_out);
}

// round 3
// speedup vs baseline: 1.1971x; 1.1971x over previous
#include <cuda_runtime.h>
#include <cstddef>

// Problem constants
#define B_TOT   16384
#define T_STEPS 128
#define F_IN    12
#define H1      64
#define H2      128
#define G0      256   // 4*H1
#define G1      512   // 4*H2
#define BT      64    // batch tile per block
#define NTHREADS 256

typedef unsigned long long u64;

// ---------------------------------------------------------------------------
// Packed f32x2 helpers (Blackwell paired-FP32 path; ptxas never auto-emits)
// ---------------------------------------------------------------------------
__device__ __forceinline__ void ffma2(u64& d, u64 a, u64 b) {
    asm("fma.rn.f32x2 %0, %1, %2, %0;" : "+l"(d) : "l"(a), "l"(b));
}
__device__ __forceinline__ u64 dup2(float v) {
    u64 r; asm("mov.b64 %0, {%1, %1};" : "=l"(r) : "f"(v)); return r;
}
__device__ __forceinline__ float2 unpk(u64 v) {
    float2 r; asm("mov.b64 {%0, %1}, %2;" : "=f"(r.x), "=f"(r.y) : "l"(v)); return r;
}

// ---------------------------------------------------------------------------
// Transposed weight scratch (device globals -> no allocation needed).
// Layout: Wt[k][j], 16B-aligned so [k*G + g*H + jcol0] is a clean 128-bit load.
// ---------------------------------------------------------------------------
__device__ __align__(16) float g_Wt0x[F_IN * G0];
__device__ __align__(16) float g_Wt0h[H1 * G0];
__device__ __align__(16) float g_Wt1a[H1 * G1];
__device__ __align__(16) float g_Wt1h[H2 * G1];
__device__ __align__(16) float g_b0[G0];
__device__ __align__(16) float g_b1[G1];

__global__ void repack_kernel(const float* __restrict__ W_ih0, const float* __restrict__ W_hh0,
                              const float* __restrict__ b_ih0, const float* __restrict__ b_hh0,
                              const float* __restrict__ W_ih1, const float* __restrict__ W_hh1,
                              const float* __restrict__ b_ih1, const float* __restrict__ b_hh1)
{
    int tid = blockIdx.x * blockDim.x + threadIdx.x;
    int stride = gridDim.x * blockDim.x;
    for (int idx = tid; idx < F_IN * G0; idx += stride) {
        int k = idx / G0, j = idx % G0;
        g_Wt0x[idx] = W_ih0[j * F_IN + k];
    }
    for (int idx = tid; idx < H1 * G0; idx += stride) {
        int k = idx / G0, j = idx % G0;
        g_Wt0h[idx] = W_hh0[j * H1 + k];
    }
    for (int idx = tid; idx < H1 * G1; idx += stride) {
        int k = idx / G1, j = idx % G1;
        g_Wt1a[idx] = W_ih1[j * H1 + k];
    }
    for (int idx = tid; idx < H2 * G1; idx += stride) {
        int k = idx / G1, j = idx % G1;
        g_Wt1h[idx] = W_hh1[j * H2 + k];
    }
    for (int idx = tid; idx < G0; idx += stride) g_b0[idx] = b_ih0[idx] + b_hh0[idx];
    for (int idx = tid; idx < G1; idx += stride) g_b1[idx] = b_ih1[idx] + b_hh1[idx];
}

// Fast activations: MUFU.EX2 + MUFU.RCP based; rel err ~1e-6 << 1e-3 tolerance.
__device__ __forceinline__ float sigm(float x) {
    return __fdividef(1.0f, 1.0f + __expf(-x));
}
__device__ __forceinline__ float tanh_f(float x) {
    return 1.0f - __fdividef(2.0f, 1.0f + __expf(2.0f * x));
}

// ---------------------------------------------------------------------------
// Main persistent kernel: one block = 64 batch elements for all 128 steps.
// eg = tid>>4 owns elements e0..e0+3; ng = tid&15 owns unit cols jcol0..+3.
// Cell states c live in registers across all timesteps. All GEMM FMAs are
// packed f32x2 (pairs along the unit dimension).
// ---------------------------------------------------------------------------
__global__ __launch_bounds__(NTHREADS, 2) void lstm_kernel(
    const float* __restrict__ xin,
    const float* __restrict__ Wd1, const float* __restrict__ bd1,
    const float* __restrict__ Wd2, const float* __restrict__ bd2,
    float* __restrict__ out)
{
    extern __shared__ float sm[];
    float* sx  = sm;                     // BT * 13
    float* sh0 = sx + BT * 13;           // BT * 65
    float* sh1 = sh0 + BT * 65;          // 2 * BT * 129
    float* red = sh1 + 2 * BT * 129;     // NTHREADS

    const int tid = threadIdx.x;
    const int eg = tid >> 4;
    const int ng = tid & 15;
    const int e0 = eg * 4;
    const int ebase = blockIdx.x * BT;
    const int jcol0 = ng * 4;

    // Persistent cell states in registers (scalar fp32)
    float c0r[4][4];
    float c1r[4][8];
    #pragma unroll
    for (int e = 0; e < 4; e++) {
        #pragma unroll
        for (int u = 0; u < 4; u++) c0r[e][u] = 0.0f;
        #pragma unroll
        for (int u = 0; u < 8; u++) c1r[e][u] = 0.0f;
    }

    for (int i = tid; i < BT * 65; i += NTHREADS) sh0[i] = 0.0f;
    for (int i = tid; i < 2 * BT * 129; i += NTHREADS) sh1[i] = 0.0f;
    __syncthreads();

    int buf = 0;
    for (int t = 0; t < T_STEPS; t++) {
        // ---- stage x_t (768 floats = 3 per thread) ----
        #pragma unroll
        for (int i = 0; i < 3; i++) {
            int idx = tid + i * NTHREADS;
            int e = idx / F_IN, f = idx - e * F_IN;
            sx[e * 13 + f] = xin[((size_t)(ebase + e) * T_STEPS + t) * F_IN + f];
        }

        // ================= Layer 0 =================
        // acc[e][g*2 + half]: packed pair = units (jcol0+2h, jcol0+2h+1)
        u64 acc[4][8];
        #pragma unroll
        for (int g = 0; g < 4; g++) {
            ulonglong2 b = *(const ulonglong2*)&g_b0[g * H1 + jcol0];
            #pragma unroll
            for (int e = 0; e < 4; e++) { acc[e][g * 2] = b.x; acc[e][g * 2 + 1] = b.y; }
        }
        // hh part (reads OLD h0) — before the barrier
        #pragma unroll 2
        for (int k = 0; k < H1; k++) {
            ulonglong2 w[4];
            #pragma unroll
            for (int g = 0; g < 4; g++)
                w[g] = *(const ulonglong2*)&g_Wt0h[k * G0 + g * H1 + jcol0];
            #pragma unroll
            for (int e = 0; e < 4; e++) {
                u64 hp = dup2(sh0[(e0 + e) * 65 + k]);
                #pragma unroll
                for (int g = 0; g < 4; g++) {
                    ffma2(acc[e][g * 2 + 0], w[g].x, hp);
                    ffma2(acc[e][g * 2 + 1], w[g].y, hp);
                }
            }
        }
        __syncthreads();   // x_t visible; all threads done reading old h0
        // ih part (reads x_t)
        #pragma unroll
        for (int k = 0; k < F_IN; k++) {
            ulonglong2 w[4];
            #pragma unroll
            for (int g = 0; g < 4; g++)
                w[g] = *(const ulonglong2*)&g_Wt0x[k * G0 + g * H1 + jcol0];
            #pragma unroll
            for (int e = 0; e < 4; e++) {
                u64 xp = dup2(sx[(e0 + e) * 13 + k]);
                #pragma unroll
                for (int g = 0; g < 4; g++) {
                    ffma2(acc[e][g * 2 + 0], w[g].x, xp);
                    ffma2(acc[e][g * 2 + 1], w[g].y, xp);
                }
            }
        }
        // elementwise update; write new h0 (safe: old h0 reads done at barrier)
        #pragma unroll
        for (int e = 0; e < 4; e++) {
            #pragma unroll
            for (int up = 0; up < 2; up++) {
                float2 iv = unpk(acc[e][0 * 2 + up]);
                float2 fv = unpk(acc[e][1 * 2 + up]);
                float2 gv = unpk(acc[e][2 * 2 + up]);
                float2 ov = unpk(acc[e][3 * 2 + up]);
                {
                    float c = fmaf(sigm(fv.x), c0r[e][up * 2 + 0], sigm(iv.x) * tanh_f(gv.x));
                    c0r[e][up * 2 + 0] = c;
                    sh0[(e0 + e) * 65 + jcol0 + up * 2 + 0] = sigm(ov.x) * tanh_f(c);
                }
                {
                    float c = fmaf(sigm(fv.y), c0r[e][up * 2 + 1], sigm(iv.y) * tanh_f(gv.y));
                    c0r[e][up * 2 + 1] = c;
                    sh0[(e0 + e) * 65 + jcol0 + up * 2 + 1] = sigm(ov.y) * tanh_f(c);
                }
            }
        }
        __syncthreads();   // new h0 visible

        // ================= Layer 1 (two 64-unit passes) =================
        const float* h1old = sh1 + buf * BT * 129;
        float* h1new = sh1 + (buf ^ 1) * BT * 129;
        #pragma unroll 1
        for (int p = 0; p < 2; p++) {
            u64 a1[4][8];
            #pragma unroll
            for (int g = 0; g < 4; g++) {
                ulonglong2 b = *(const ulonglong2*)&g_b1[g * H2 + p * 64 + jcol0];
                #pragma unroll
                for (int e = 0; e < 4; e++) { a1[e][g * 2] = b.x; a1[e][g * 2 + 1] = b.y; }
            }
            // input = new h0
            #pragma unroll 2
            for (int k = 0; k < H1; k++) {
                ulonglong2 w[4];
                #pragma unroll
                for (int g = 0; g < 4; g++)
                    w[g] = *(const ulonglong2*)&g_Wt1a[k * G1 + g * H2 + p * 64 + jcol0];
                #pragma unroll
                for (int e = 0; e < 4; e++) {
                    u64 hp = dup2(sh0[(e0 + e) * 65 + k]);
                    #pragma unroll
                    for (int g = 0; g < 4; g++) {
                        ffma2(a1[e][g * 2 + 0], w[g].x, hp);
                        ffma2(a1[e][g * 2 + 1], w[g].y, hp);
                    }
                }
            }
            // recurrent = old h1
            #pragma unroll 2
            for (int k = 0; k < H2; k++) {
                ulonglong2 w[4];
                #pragma unroll
                for (int g = 0; g < 4; g++)
                    w[g] = *(const ulonglong2*)&g_Wt1h[k * G1 + g * H2 + p * 64 + jcol0];
                #pragma unroll
                for (int e = 0; e < 4; e++) {
                    u64 hp = dup2(h1old[(e0 + e) * 129 + k]);
                    #pragma unroll
                    for (int g = 0; g < 4; g++) {
                        ffma2(a1[e][g * 2 + 0], w[g].x, hp);
                        ffma2(a1[e][g * 2 + 1], w[g].y, hp);
                    }
                }
            }
            // update; write to the OTHER buffer (no barrier needed between passes)
            #pragma unroll
            for (int e = 0; e < 4; e++) {
                #pragma unroll
                for (int up = 0; up < 2; up++) {
                    float2 iv = unpk(a1[e][0 * 2 + up]);
                    float2 fv = unpk(a1[e][1 * 2 + up]);
                    float2 gv = unpk(a1[e][2 * 2 + up]);
                    float2 ov = unpk(a1[e][3 * 2 + up]);
                    {
                        int u = p * 4 + up * 2 + 0;
                        float c = fmaf(sigm(fv.x), c1r[e][u], sigm(iv.x) * tanh_f(gv.x));
                        c1r[e][u] = c;
                        h1new[(e0 + e) * 129 + p * 64 + jcol0 + up * 2 + 0] = sigm(ov.x) * tanh_f(c);
                    }
                    {
                        int u = p * 4 + up * 2 + 1;
                        float c = fmaf(sigm(fv.y), c1r[e][u], sigm(iv.y) * tanh_f(gv.y));
                        c1r[e][u] = c;
                        h1new[(e0 + e) * 129 + p * 64 + jcol0 + up * 2 + 1] = sigm(ov.y) * tanh_f(c);
                    }
                }
            }
        }
        buf ^= 1;
        __syncthreads();   // new h1 visible for next step
    }

    // ================= Final dense head =================
    const float* h1f = sh1 + buf * BT * 129;
    {
        int e = tid >> 2;      // 0..63
        int q = tid & 3;       // quarter of the 64 m-values
        float s = 0.0f;
        for (int m = q * 16; m < q * 16 + 16; m++) {
            float d = bd1[m];
            #pragma unroll 4
            for (int j = 0; j < H2; j++)
                d = fmaf(Wd1[m * H2 + j], h1f[e * 129 + j], d);
            s = fmaf(Wd2[m], d, s);
        }
        red[tid] = s;
        __syncthreads();
        if (q == 0)
            out[ebase + e] = red[tid] + red[tid + 1] + red[tid + 2] + red[tid + 3] + bd2[0];
    }
}

// ---------------------------------------------------------------------------
// Launch
// ---------------------------------------------------------------------------
extern "C" void kernel_launch(void* const* d_in, const int* in_sizes, int n_in,
                              void* d_out, int out_size)
{
    (void)in_sizes; (void)n_in; (void)out_size;
    const float* input_seq = (const float*)d_in[0];
    const float* W_ih0 = (const float*)d_in[1];
    const float* W_hh0 = (const float*)d_in[2];
    const float* b_ih0 = (const float*)d_in[3];
    const float* b_hh0 = (const float*)d_in[4];
    const float* W_ih1 = (const float*)d_in[5];
    const float* W_hh1 = (const float*)d_in[6];
    const float* b_ih1 = (const float*)d_in[7];
    const float* b_hh1 = (const float*)d_in[8];
    const float* W_d1  = (const float*)d_in[9];
    const float* b_d1  = (const float*)d_in[10];
    const float* W_d2  = (const float*)d_in[11];
    const float* b_d2  = (const float*)d_in[12];

    const int smem_bytes = (BT * 13 + BT * 65 + 2 * BT * 129 + NTHREADS) * sizeof(float); // 87040
    cudaFuncSetAttribute(lstm_kernel, cudaFuncAttributeMaxDynamicSharedMemorySize, smem_bytes);

    repack_kernel<<<64, 256>>>(W_ih0, W_hh0, b_ih0, b_hh0, W_ih1, W_hh1, b_ih1, b_hh1);
    lstm_kernel<<<B_TOT / BT, NTHREADS, smem_bytes>>>(
        input_seq, W_d1, b_d1, W_d2, b_d2, (float*)d_out);
}

// round 6
// speedup vs baseline: 3.6084x; 3.0144x over previous
#include <cuda_runtime.h>
#include <cuda_bf16.h>
#include <cstddef>

// Problem constants
#define B_TOT   16384
#define T_STEPS 128
#define F_IN    12
#define H1      64
#define H2      128
#define BT      64
#define NTH     512
#define GRID    (B_TOT / BT)   // 256

// A-buffer geometry (bf16 planes in smem): cols [0,16)=x(pad), [16,80)=h0, [80,208)=h1
#define H0OFF   16
#define H1OFF   80
#define ASTRIDE 216            // padded row stride in elements (432B -> conflict-free)

// ---------------------------------------------------------------------------
// Device-global scratch (weights only; ~480KB)
// ---------------------------------------------------------------------------
__device__ uint4 g_WfragL0[5 * 32 * 32];    // [kt][nt][lane] -> (bh0,bh1,bl0,bl1)
__device__ uint4 g_WfragL1[12 * 64 * 32];
__device__ float g_b0i[256];                // gate-interleaved biases: col = 4u+g
__device__ float g_b1i[512];

// ---------------------------------------------------------------------------
// Helpers
// ---------------------------------------------------------------------------
__device__ __forceinline__ unsigned pack_bf2(float a, float b) {
    __nv_bfloat162 t = __floats2bfloat162_rn(a, b);   // .x = a (low), .y = b (high)
    unsigned r; memcpy(&r, &t, 4); return r;
}
__device__ __forceinline__ float sigm(float x) {
    return __fdividef(1.0f, 1.0f + __expf(-x));
}
__device__ __forceinline__ float tanh_f(float x) {
    return 1.0f - __fdividef(2.0f, 1.0f + __expf(2.0f * x));
}

__device__ __forceinline__ void mma16816(float* d, const unsigned* a, unsigned b0, unsigned b1) {
    asm volatile(
        "mma.sync.aligned.m16n8k16.row.col.f32.bf16.bf16.f32 "
        "{%0,%1,%2,%3}, {%4,%5,%6,%7}, {%8,%9}, {%0,%1,%2,%3};\n"
        : "+f"(d[0]), "+f"(d[1]), "+f"(d[2]), "+f"(d[3])
        : "r"(a[0]), "r"(a[1]), "r"(a[2]), "r"(a[3]), "r"(b0), "r"(b1));
}

// A fragment (m16k16, row-major): a0=[r][c..c+1] a1=[r+8][c..] a2=[r][c+8..] a3=[r+8][c+8..]
__device__ __forceinline__ void ldA(unsigned* a, const __nv_bfloat16* plane, int row0, int colbase) {
    a[0] = *(const unsigned*)&plane[row0 * ASTRIDE + colbase];
    a[1] = *(const unsigned*)&plane[(row0 + 8) * ASTRIDE + colbase];
    a[2] = *(const unsigned*)&plane[row0 * ASTRIDE + colbase + 8];
    a[3] = *(const unsigned*)&plane[(row0 + 8) * ASTRIDE + colbase + 8];
}

// ---------------------------------------------------------------------------
// Repack: weights -> mma B-fragment order, gate-interleaved (col = 4u + g)
// B frag (k16 x n8, "col"): lane t, reg r, half h -> k = (t%4)*2 + r*8 + h, n = t/4
// ---------------------------------------------------------------------------
__global__ void repack(const float* __restrict__ W_ih0, const float* __restrict__ W_hh0,
                       const float* __restrict__ b_ih0, const float* __restrict__ b_hh0,
                       const float* __restrict__ W_ih1, const float* __restrict__ W_hh1,
                       const float* __restrict__ b_ih1, const float* __restrict__ b_hh1)
{
    const int T0 = 5 * 32 * 32, T1 = 12 * 64 * 32;
    for (int idx = blockIdx.x * blockDim.x + threadIdx.x;
         idx < T0 + T1 + 256 + 512; idx += gridDim.x * blockDim.x) {
        if (idx < T0 + T1) {
            int lidx = idx, isL1 = 0;
            if (lidx >= T0) { lidx -= T0; isL1 = 1; }
            int lane = lidx & 31;
            int ntcnt = isL1 ? 64 : 32;
            int nt = (lidx >> 5) % ntcnt;
            int kt = (lidx >> 5) / ntcnt;
            int n = nt * 8 + (lane >> 2);                // interleaved col = 4u+g
            float v[4];
            #pragma unroll
            for (int q = 0; q < 4; q++) {
                int k = kt * 16 + (lane & 3) * 2 + (q >> 1) * 8 + (q & 1);
                float val;
                if (!isL1) {
                    int row = (n & 3) * H1 + (n >> 2);   // g*H1 + u
                    if (k < 16) val = (k < F_IN) ? W_ih0[row * F_IN + k] : 0.0f;
                    else        val = W_hh0[row * H1 + (k - 16)];
                } else {
                    int row = (n & 3) * H2 + (n >> 2);   // g*H2 + u
                    if (k < 64) val = W_ih1[row * H1 + k];
                    else        val = W_hh1[row * H2 + (k - 64)];
                }
                v[q] = val;
            }
            float hi[4], lo[4];
            #pragma unroll
            for (int q = 0; q < 4; q++) {
                __nv_bfloat16 h = __float2bfloat16(v[q]);
                hi[q] = __bfloat162float(h);
                lo[q] = v[q] - hi[q];
            }
            uint4 w;
            w.x = pack_bf2(hi[0], hi[1]);   // Bh reg0
            w.y = pack_bf2(hi[2], hi[3]);   // Bh reg1
            w.z = pack_bf2(lo[0], lo[1]);   // Bl reg0
            w.w = pack_bf2(lo[2], lo[3]);   // Bl reg1
            if (!isL1) g_WfragL0[(kt * 32 + nt) * 32 + lane] = w;
            else       g_WfragL1[(kt * 64 + nt) * 32 + lane] = w;
        } else if (idx < T0 + T1 + 256) {
            int n = idx - (T0 + T1);
            int row = (n & 3) * H1 + (n >> 2);
            g_b0i[n] = b_ih0[row] + b_hh0[row];
        } else {
            int n = idx - (T0 + T1 + 256);
            int row = (n & 3) * H2 + (n >> 2);
            g_b1i[n] = b_ih1[row] + b_hh1[row];
        }
    }
}

// ---------------------------------------------------------------------------
// Main kernel: BT=64 batch/block, 16 warps = (mt 0..3) x (ng 0..3).
// L0: M=64 N=256 K=80 (x||h0); L1: M=64 N=512 K=192 (h0||h1).
// 3-term bf16 split MMA, fp32 accumulate. c-state in smem.
// x is loaded as raw fp32 and hi/lo-split in-register at staging time.
// ---------------------------------------------------------------------------
__global__ __launch_bounds__(NTH, 1) void lstm_mma(
    const float* __restrict__ xin,
    const float* __restrict__ Wd1, const float* __restrict__ bd1,
    const float* __restrict__ Wd2, const float* __restrict__ bd2,
    float* __restrict__ out)
{
    extern __shared__ unsigned char smraw[];
    __nv_bfloat16* Ahi = (__nv_bfloat16*)smraw;                        // 64*216 bf16
    __nv_bfloat16* Alo = Ahi + 64 * ASTRIDE;
    float* bias0 = (float*)(smraw + (size_t)2 * 64 * ASTRIDE * 2);     // 256
    float* bias1 = bias0 + 256;                                        // 512
    float* csm   = bias1 + 512;                                        // 24*512

    const int tid  = threadIdx.x;
    const int wid  = tid >> 5, lane = tid & 31;
    const int mt   = wid & 3, ng = wid >> 2;
    const int grp  = lane >> 2;          // 0..7
    const int qc   = lane & 3;           // 0..3
    const int par  = lane & 1;           // gate-pair parity
    const int row0 = mt * 16 + grp;
    const int ebase = blockIdx.x * BT;

    // init smem
    for (int i = tid; i < 256; i += NTH) bias0[i] = g_b0i[i];
    for (int i = tid; i < 512; i += NTH) bias1[i] = g_b1i[i];
    for (int i = tid; i < 24 * 512; i += NTH) csm[i] = 0.0f;
    for (int i = tid; i < 2 * 64 * ASTRIDE; i += NTH)
        ((unsigned short*)Ahi)[i] = 0;   // +0.0 bf16
    __syncthreads();

    for (int t = 0; t < T_STEPS; t++) {
        // ---- stage x_t: load fp32, split to bf16 hi/lo (1024 vals, 2/thread) ----
        #pragma unroll
        for (int i = 0; i < 2; i++) {
            int idx = tid + i * NTH;         // 0..1023
            int r = idx >> 4, c = idx & 15;
            float v = 0.0f;
            if (c < F_IN)
                v = xin[((size_t)(ebase + r) * T_STEPS + t) * F_IN + c];
            __nv_bfloat16 h = __float2bfloat16(v);
            Ahi[r * ASTRIDE + c] = h;
            Alo[r * ASTRIDE + c] = __float2bfloat16(v - __bfloat162float(h));
        }
        __syncthreads();   // x visible; prev-step h0/h1 long since visible

        // ================= Layer 0 GEMM: K=80 over cols [0,80) =================
        float d0[8][4];
        #pragma unroll
        for (int j = 0; j < 8; j++) {
            float2 b = *(const float2*)&bias0[ng * 64 + j * 8 + qc * 2];
            d0[j][0] = b.x; d0[j][1] = b.y; d0[j][2] = b.x; d0[j][3] = b.y;
        }
        #pragma unroll
        for (int kt = 0; kt < 5; kt++) {
            unsigned ah[4], al[4];
            ldA(ah, Ahi, row0, kt * 16 + qc * 2);
            ldA(al, Alo, row0, kt * 16 + qc * 2);
            #pragma unroll
            for (int j = 0; j < 8; j++) {
                uint4 w = g_WfragL0[(kt * 32 + ng * 8 + j) * 32 + lane];
                mma16816(d0[j], ah, w.x, w.y);   // Ah*Bh
                mma16816(d0[j], ah, w.z, w.w);   // Ah*Bl
                mma16816(d0[j], al, w.x, w.y);   // Al*Bh
            }
        }
        __syncthreads();   // all L0 reads done (incl. h0_prev)

        // ---- L0 elementwise: pair-exchange -> each thread one (unit,row) ----
        #pragma unroll
        for (int j = 0; j < 8; j++) {
            float s0 = par ? d0[j][0] : d0[j][2];
            float s1 = par ? d0[j][1] : d0[j][3];
            float v0 = __shfl_xor_sync(0xffffffffu, s0, 1);
            float v1 = __shfl_xor_sync(0xffffffffu, s1, 1);
            float zi, zf, zg, zo;
            if (par == 0) { zi = d0[j][0]; zf = d0[j][1]; zg = v0; zo = v1; }
            else          { zi = v0; zf = v1; zg = d0[j][2]; zo = d0[j][3]; }
            float c = csm[j * 512 + tid];
            c = fmaf(sigm(zf), c, sigm(zi) * tanh_f(zg));
            csm[j * 512 + tid] = c;
            float h = sigm(zo) * tanh_f(c);
            int u  = ng * 16 + j * 2 + (qc >> 1);
            int rr = row0 + (par ? 8 : 0);
            __nv_bfloat16 hh = __float2bfloat16(h);
            Ahi[rr * ASTRIDE + H0OFF + u] = hh;
            Alo[rr * ASTRIDE + H0OFF + u] = __float2bfloat16(h - __bfloat162float(hh));
        }
        __syncthreads();   // h0 visible

        // ================= Layer 1 GEMM: K=192 over cols [16,208) =================
        float d1[16][4];
        #pragma unroll
        for (int j = 0; j < 16; j++) {
            float2 b = *(const float2*)&bias1[ng * 128 + j * 8 + qc * 2];
            d1[j][0] = b.x; d1[j][1] = b.y; d1[j][2] = b.x; d1[j][3] = b.y;
        }
        #pragma unroll
        for (int kt = 0; kt < 12; kt++) {
            unsigned ah[4], al[4];
            ldA(ah, Ahi, row0, H0OFF + kt * 16 + qc * 2);
            ldA(al, Alo, row0, H0OFF + kt * 16 + qc * 2);
            #pragma unroll
            for (int j = 0; j < 16; j++) {
                uint4 w = g_WfragL1[(kt * 64 + ng * 16 + j) * 32 + lane];
                mma16816(d1[j], ah, w.x, w.y);
                mma16816(d1[j], ah, w.z, w.w);
                mma16816(d1[j], al, w.x, w.y);
            }
        }
        __syncthreads();   // all L1 reads done (incl. h1_prev)

        // ---- L1 elementwise ----
        #pragma unroll
        for (int j = 0; j < 16; j++) {
            float s0 = par ? d1[j][0] : d1[j][2];
            float s1 = par ? d1[j][1] : d1[j][3];
            float v0 = __shfl_xor_sync(0xffffffffu, s0, 1);
            float v1 = __shfl_xor_sync(0xffffffffu, s1, 1);
            float zi, zf, zg, zo;
            if (par == 0) { zi = d1[j][0]; zf = d1[j][1]; zg = v0; zo = v1; }
            else          { zi = v0; zf = v1; zg = d1[j][2]; zo = d1[j][3]; }
            float c = csm[(8 + j) * 512 + tid];
            c = fmaf(sigm(zf), c, sigm(zi) * tanh_f(zg));
            csm[(8 + j) * 512 + tid] = c;
            float h = sigm(zo) * tanh_f(c);
            int u  = ng * 32 + j * 2 + (qc >> 1);
            int rr = row0 + (par ? 8 : 0);
            __nv_bfloat16 hh = __float2bfloat16(h);
            Ahi[rr * ASTRIDE + H1OFF + u] = hh;
            Alo[rr * ASTRIDE + H1OFF + u] = __float2bfloat16(h - __bfloat162float(hh));
        }
        // no barrier needed here: next x-copy touches disjoint cols; next L0 GEMM
        // is separated from these writes by the x barrier.
    }
    __syncthreads();   // final h1 visible to all

    // ================= Dense head =================
    {
        int e = tid >> 3, q = tid & 7;      // 64 elems x 8 partials
        float s = 0.0f;
        for (int m = q * 8; m < q * 8 + 8; m++) {
            float dsum = bd1[m];
            #pragma unroll 4
            for (int jj = 0; jj < H2; jj++) {
                float hv = __bfloat162float(Ahi[e * ASTRIDE + H1OFF + jj])
                         + __bfloat162float(Alo[e * ASTRIDE + H1OFF + jj]);
                dsum = fmaf(Wd1[m * H2 + jj], hv, dsum);
            }
            s = fmaf(Wd2[m], dsum, s);
        }
        csm[tid] = s;
        __syncthreads();
        if (q == 0) {
            float r = 0.0f;
            #pragma unroll
            for (int k = 0; k < 8; k++) r += csm[e * 8 + k];
            out[ebase + e] = r + bd2[0];
        }
    }
}

// ---------------------------------------------------------------------------
// Launch
// ---------------------------------------------------------------------------
extern "C" void kernel_launch(void* const* d_in, const int* in_sizes, int n_in,
                              void* d_out, int out_size)
{
    (void)in_sizes; (void)n_in; (void)out_size;
    const float* input_seq = (const float*)d_in[0];
    const float* W_ih0 = (const float*)d_in[1];
    const float* W_hh0 = (const float*)d_in[2];
    const float* b_ih0 = (const float*)d_in[3];
    const float* b_hh0 = (const float*)d_in[4];
    const float* W_ih1 = (const float*)d_in[5];
    const float* W_hh1 = (const float*)d_in[6];
    const float* b_ih1 = (const float*)d_in[7];
    const float* b_hh1 = (const float*)d_in[8];
    const float* W_d1  = (const float*)d_in[9];
    const float* b_d1  = (const float*)d_in[10];
    const float* W_d2  = (const float*)d_in[11];
    const float* b_d2  = (const float*)d_in[12];

    const size_t smem_bytes = (size_t)2 * 64 * ASTRIDE * 2     // A planes
                            + (256 + 512) * sizeof(float)      // biases
                            + 24 * 512 * sizeof(float);        // c state / scratch
    cudaFuncSetAttribute(lstm_mma, cudaFuncAttributeMaxDynamicSharedMemorySize, (int)smem_bytes);

    repack<<<128, 256>>>(W_ih0, W_hh0, b_ih0, b_hh0, W_ih1, W_hh1, b_ih1, b_hh1);
    lstm_mma<<<GRID, NTH, smem_bytes>>>(input_seq, W_d1, b_d1, W_d2, b_d2, (float*)d_out);
}

// round 8
// speedup vs baseline: 3.7858x; 1.0491x over previous
#include <cuda_runtime.h>
#include <cuda_bf16.h>
#include <cstddef>

// Problem constants
#define B_TOT   16384
#define T_STEPS 128
#define F_IN    12
#define H1      64
#define H2      128
#define BT      64
#define NTH     512
#define GRID    (B_TOT / BT)   // 256

// A-buffer geometry (bf16 planes in smem), stride 408:
// cols [0,16)=x, [16,80)=h0 parity0, [80,144)=h0 parity1,
//      [144,272)=h1 parity0, [272,400)=h1 parity1
#define H0B     16
#define H1B     144
#define ASTRIDE 408

// ---------------------------------------------------------------------------
// Device-global scratch (weights only; ~480KB)
// ---------------------------------------------------------------------------
__device__ uint4 g_WfragL0[5 * 32 * 32];    // [kt][nt][lane] -> (bh0,bh1,bl0,bl1)
__device__ uint4 g_WfragL1[12 * 64 * 32];
__device__ float g_b0i[256];                // gate-interleaved biases: col = 4u+g
__device__ float g_b1i[512];

// ---------------------------------------------------------------------------
// Helpers
// ---------------------------------------------------------------------------
__device__ __forceinline__ unsigned pack_bf2(float a, float b) {
    __nv_bfloat162 t = __floats2bfloat162_rn(a, b);
    unsigned r; memcpy(&r, &t, 4); return r;
}
__device__ __forceinline__ float sigm(float x) {
    return __fdividef(1.0f, 1.0f + __expf(-x));
}
__device__ __forceinline__ float tanh_f(float x) {
    return 1.0f - __fdividef(2.0f, 1.0f + __expf(2.0f * x));
}
__device__ __forceinline__ void barh(int id) {
    asm volatile("bar.sync %0, 256;" :: "r"(id) : "memory");
}

__device__ __forceinline__ void mma16816(float* d, const unsigned* a, unsigned b0, unsigned b1) {
    asm volatile(
        "mma.sync.aligned.m16n8k16.row.col.f32.bf16.bf16.f32 "
        "{%0,%1,%2,%3}, {%4,%5,%6,%7}, {%8,%9}, {%0,%1,%2,%3};\n"
        : "+f"(d[0]), "+f"(d[1]), "+f"(d[2]), "+f"(d[3])
        : "r"(a[0]), "r"(a[1]), "r"(a[2]), "r"(a[3]), "r"(b0), "r"(b1));
}

// A fragment (m16k16, row-major): a0=[r][c..c+1] a1=[r+8][c..] a2=[r][c+8..] a3=[r+8][c+8..]
__device__ __forceinline__ void ldA(unsigned* a, const __nv_bfloat16* plane, int row0, int colbase) {
    a[0] = *(const unsigned*)&plane[row0 * ASTRIDE + colbase];
    a[1] = *(const unsigned*)&plane[(row0 + 8) * ASTRIDE + colbase];
    a[2] = *(const unsigned*)&plane[row0 * ASTRIDE + colbase + 8];
    a[3] = *(const unsigned*)&plane[(row0 + 8) * ASTRIDE + colbase + 8];
}

// ---------------------------------------------------------------------------
// Repack: weights -> mma B-fragment order, gate-interleaved (col = 4u + g)
// B frag (k16 x n8, "col"): lane t, reg r, half h -> k = (t%4)*2 + r*8 + h, n = t/4
// ---------------------------------------------------------------------------
__global__ void repack(const float* __restrict__ W_ih0, const float* __restrict__ W_hh0,
                       const float* __restrict__ b_ih0, const float* __restrict__ b_hh0,
                       const float* __restrict__ W_ih1, const float* __restrict__ W_hh1,
                       const float* __restrict__ b_ih1, const float* __restrict__ b_hh1)
{
    const int T0 = 5 * 32 * 32, T1 = 12 * 64 * 32;
    for (int idx = blockIdx.x * blockDim.x + threadIdx.x;
         idx < T0 + T1 + 256 + 512; idx += gridDim.x * blockDim.x) {
        if (idx < T0 + T1) {
            int lidx = idx, isL1 = 0;
            if (lidx >= T0) { lidx -= T0; isL1 = 1; }
            int lane = lidx & 31;
            int ntcnt = isL1 ? 64 : 32;
            int nt = (lidx >> 5) % ntcnt;
            int kt = (lidx >> 5) / ntcnt;
            int n = nt * 8 + (lane >> 2);
            float v[4];
            #pragma unroll
            for (int q = 0; q < 4; q++) {
                int k = kt * 16 + (lane & 3) * 2 + (q >> 1) * 8 + (q & 1);
                float val;
                if (!isL1) {
                    int row = (n & 3) * H1 + (n >> 2);
                    if (k < 16) val = (k < F_IN) ? W_ih0[row * F_IN + k] : 0.0f;
                    else        val = W_hh0[row * H1 + (k - 16)];
                } else {
                    int row = (n & 3) * H2 + (n >> 2);
                    if (k < 64) val = W_ih1[row * H1 + k];
                    else        val = W_hh1[row * H2 + (k - 64)];
                }
                v[q] = val;
            }
            float hi[4], lo[4];
            #pragma unroll
            for (int q = 0; q < 4; q++) {
                __nv_bfloat16 h = __float2bfloat16(v[q]);
                hi[q] = __bfloat162float(h);
                lo[q] = v[q] - hi[q];
            }
            uint4 w;
            w.x = pack_bf2(hi[0], hi[1]);
            w.y = pack_bf2(hi[2], hi[3]);
            w.z = pack_bf2(lo[0], lo[1]);
            w.w = pack_bf2(lo[2], lo[3]);
            if (!isL1) g_WfragL0[(kt * 32 + nt) * 32 + lane] = w;
            else       g_WfragL1[(kt * 64 + nt) * 32 + lane] = w;
        } else if (idx < T0 + T1 + 256) {
            int n = idx - (T0 + T1);
            int row = (n & 3) * H1 + (n >> 2);
            g_b0i[n] = b_ih0[row] + b_hh0[row];
        } else {
            int n = idx - (T0 + T1 + 256);
            int row = (n & 3) * H2 + (n >> 2);
            g_b1i[n] = b_ih1[row] + b_hh1[row];
        }
    }
}

// ---------------------------------------------------------------------------
// Main kernel: BT=64 batch/block, TWO independent 32-row halves of 8 warps.
// Halves sync only via named barriers (bar.sync 1/2, 256) -> intra-SM overlap.
// h0/h1 double-buffered by column parity -> only 2 barriers per step.
// 3-term bf16 split MMA, fp32 accumulate. c-state in smem.
// ---------------------------------------------------------------------------
__global__ __launch_bounds__(NTH, 1) void lstm_mma(
    const float* __restrict__ xin,
    const float* __restrict__ Wd1, const float* __restrict__ bd1,
    const float* __restrict__ Wd2, const float* __restrict__ bd2,
    float* __restrict__ out)
{
    extern __shared__ unsigned char smraw[];
    __nv_bfloat16* Ahi = (__nv_bfloat16*)smraw;                        // 64*408 bf16
    __nv_bfloat16* Alo = Ahi + 64 * ASTRIDE;
    float* bias0 = (float*)(smraw + (size_t)2 * 64 * ASTRIDE * 2);     // 256
    float* bias1 = bias0 + 256;                                        // 512
    float* csm   = bias1 + 512;                                        // 24*512

    const int tid  = threadIdx.x;
    const int wid  = tid >> 5, lane = tid & 31;
    const int half = wid >> 3;           // 0 or 1
    const int wl   = wid & 7;
    const int mt   = wl & 1, ng = wl >> 1;
    const int grp  = lane >> 2;          // 0..7
    const int qc   = lane & 3;           // 0..3
    const int par  = lane & 1;
    const int row0 = half * 32 + mt * 16 + grp;
    const int ebase = blockIdx.x * BT;
    const int tl   = tid & 255;          // tid within half
    const int barid = 1 + half;

    // init smem
    for (int i = tid; i < 256; i += NTH) bias0[i] = g_b0i[i];
    for (int i = tid; i < 512; i += NTH) bias1[i] = g_b1i[i];
    for (int i = tid; i < 24 * 512; i += NTH) csm[i] = 0.0f;
    for (int i = tid; i < 2 * 64 * ASTRIDE; i += NTH)
        ((unsigned short*)Ahi)[i] = 0;   // +0.0 bf16
    __syncthreads();

    for (int t = 0; t < T_STEPS; t++) {
        const int h0r = H0B + (t & 1) * 64;          // read-parity h0
        const int h0w = H0B + ((t + 1) & 1) * 64;    // write-parity h0
        const int h1r = H1B + (t & 1) * 128;
        const int h1w = H1B + ((t + 1) & 1) * 128;

        // ---- stage x_t for this half (32 rows x 16 cols, 2 vals/thread) ----
        #pragma unroll
        for (int i = 0; i < 2; i++) {
            int idx = tl + i * 256;                  // 0..511
            int r = half * 32 + (idx >> 4), c = idx & 15;
            float v = 0.0f;
            if (c < F_IN)
                v = xin[((size_t)(ebase + r) * T_STEPS + t) * F_IN + c];
            __nv_bfloat16 h = __float2bfloat16(v);
            Ahi[r * ASTRIDE + c] = h;
            Alo[r * ASTRIDE + c] = __float2bfloat16(v - __bfloat162float(h));
        }
        barh(barid);   // x + h1[new from t-1] + h0[new from t-1] visible in half

        // ================= Layer 0 GEMM: K=80 = x(16) || h0_old(64) ========
        float d0[8][4];
        #pragma unroll
        for (int j = 0; j < 8; j++) {
            float2 b = *(const float2*)&bias0[ng * 64 + j * 8 + qc * 2];
            d0[j][0] = b.x; d0[j][1] = b.y; d0[j][2] = b.x; d0[j][3] = b.y;
        }
        #pragma unroll
        for (int kt = 0; kt < 5; kt++) {
            int colbase = (kt == 0) ? (qc * 2) : (h0r + (kt - 1) * 16 + qc * 2);
            unsigned ah[4], al[4];
            ldA(ah, Ahi, row0, colbase);
            ldA(al, Alo, row0, colbase);
            #pragma unroll
            for (int j = 0; j < 8; j++) {
                uint4 w = g_WfragL0[(kt * 32 + ng * 8 + j) * 32 + lane];
                mma16816(d0[j], ah, w.x, w.y);   // Ah*Bh
                mma16816(d0[j], ah, w.z, w.w);   // Ah*Bl
                mma16816(d0[j], al, w.x, w.y);   // Al*Bh
            }
        }

        // ---- L0 elementwise -> h0[write parity] (no barrier needed) ----
        #pragma unroll
        for (int j = 0; j < 8; j++) {
            float s0 = par ? d0[j][0] : d0[j][2];
            float s1 = par ? d0[j][1] : d0[j][3];
            float v0 = __shfl_xor_sync(0xffffffffu, s0, 1);
            float v1 = __shfl_xor_sync(0xffffffffu, s1, 1);
            float zi, zf, zg, zo;
            if (par == 0) { zi = d0[j][0]; zf = d0[j][1]; zg = v0; zo = v1; }
            else          { zi = v0; zf = v1; zg = d0[j][2]; zo = d0[j][3]; }
            float c = csm[j * 512 + tid];
            c = fmaf(sigm(zf), c, sigm(zi) * tanh_f(zg));
            csm[j * 512 + tid] = c;
            float h = sigm(zo) * tanh_f(c);
            int u  = ng * 16 + j * 2 + (qc >> 1);
            int rr = row0 + (par ? 8 : 0);
            __nv_bfloat16 hh = __float2bfloat16(h);
            Ahi[rr * ASTRIDE + h0w + u] = hh;
            Alo[rr * ASTRIDE + h0w + u] = __float2bfloat16(h - __bfloat162float(hh));
        }
        barh(barid);   // h0[new] complete within half

        // ================= Layer 1 GEMM: K=192 = h0_new(64) || h1_old(128) ==
        float d1[16][4];
        #pragma unroll
        for (int j = 0; j < 16; j++) {
            float2 b = *(const float2*)&bias1[ng * 128 + j * 8 + qc * 2];
            d1[j][0] = b.x; d1[j][1] = b.y; d1[j][2] = b.x; d1[j][3] = b.y;
        }
        #pragma unroll
        for (int kt = 0; kt < 12; kt++) {
            int colbase = (kt < 4) ? (h0w + kt * 16 + qc * 2)
                                   : (h1r + (kt - 4) * 16 + qc * 2);
            unsigned ah[4], al[4];
            ldA(ah, Ahi, row0, colbase);
            ldA(al, Alo, row0, colbase);
            #pragma unroll
            for (int j = 0; j < 16; j++) {
                uint4 w = g_WfragL1[(kt * 64 + ng * 16 + j) * 32 + lane];
                mma16816(d1[j], ah, w.x, w.y);
                mma16816(d1[j], ah, w.z, w.w);
                mma16816(d1[j], al, w.x, w.y);
            }
        }

        // ---- L1 elementwise -> h1[write parity] (no barrier; next bar covers) ----
        #pragma unroll
        for (int j = 0; j < 16; j++) {
            float s0 = par ? d1[j][0] : d1[j][2];
            float s1 = par ? d1[j][1] : d1[j][3];
            float v0 = __shfl_xor_sync(0xffffffffu, s0, 1);
            float v1 = __shfl_xor_sync(0xffffffffu, s1, 1);
            float zi, zf, zg, zo;
            if (par == 0) { zi = d1[j][0]; zf = d1[j][1]; zg = v0; zo = v1; }
            else          { zi = v0; zf = v1; zg = d1[j][2]; zo = d1[j][3]; }
            float c = csm[(8 + j) * 512 + tid];
            c = fmaf(sigm(zf), c, sigm(zi) * tanh_f(zg));
            csm[(8 + j) * 512 + tid] = c;
            float h = sigm(zo) * tanh_f(c);
            int u  = ng * 32 + j * 2 + (qc >> 1);
            int rr = row0 + (par ? 8 : 0);
            __nv_bfloat16 hh = __float2bfloat16(h);
            Ahi[rr * ASTRIDE + h1w + u] = hh;
            Alo[rr * ASTRIDE + h1w + u] = __float2bfloat16(h - __bfloat162float(hh));
        }
    }
    __syncthreads();   // both halves done; final h1 (parity 0) visible block-wide

    // ================= Dense head =================
    {
        int e = tid >> 3, q = tid & 7;      // 64 elems x 8 partials
        float s = 0.0f;
        for (int m = q * 8; m < q * 8 + 8; m++) {
            float dsum = bd1[m];
            #pragma unroll 4
            for (int jj = 0; jj < H2; jj++) {
                float hv = __bfloat162float(Ahi[e * ASTRIDE + H1B + jj])
                         + __bfloat162float(Alo[e * ASTRIDE + H1B + jj]);
                dsum = fmaf(Wd1[m * H2 + jj], hv, dsum);
            }
            s = fmaf(Wd2[m], dsum, s);
        }
        csm[tid] = s;
        __syncthreads();
        if (q == 0) {
            float r = 0.0f;
            #pragma unroll
            for (int k = 0; k < 8; k++) r += csm[e * 8 + k];
            out[ebase + e] = r + bd2[0];
        }
    }
}

// ---------------------------------------------------------------------------
// Launch
// ---------------------------------------------------------------------------
extern "C" void kernel_launch(void* const* d_in, const int* in_sizes, int n_in,
                              void* d_out, int out_size)
{
    (void)in_sizes; (void)n_in; (void)out_size;
    const float* input_seq = (const float*)d_in[0];
    const float* W_ih0 = (const float*)d_in[1];
    const float* W_hh0 = (const float*)d_in[2];
    const float* b_ih0 = (const float*)d_in[3];
    const float* b_hh0 = (const float*)d_in[4];
    const float* W_ih1 = (const float*)d_in[5];
    const float* W_hh1 = (const float*)d_in[6];
    const float* b_ih1 = (const float*)d_in[7];
    const float* b_hh1 = (const float*)d_in[8];
    const float* W_d1  = (const float*)d_in[9];
    const float* b_d1  = (const float*)d_in[10];
    const float* W_d2  = (const float*)d_in[11];
    const float* b_d2  = (const float*)d_in[12];

    const size_t smem_bytes = (size_t)2 * 64 * ASTRIDE * 2     // A planes (104448)
                            + (256 + 512) * sizeof(float)      // biases   (3072)
                            + 24 * 512 * sizeof(float);        // c state  (49152)
    cudaFuncSetAttribute(lstm_mma, cudaFuncAttributeMaxDynamicSharedMemorySize, (int)smem_bytes);

    repack<<<128, 256>>>(W_ih0, W_hh0, b_ih0, b_hh0, W_ih1, W_hh1, b_ih1, b_hh1);
    lstm_mma<<<GRID, NTH, smem_bytes>>>(input_seq, W_d1, b_d1, W_d2, b_d2, (float*)d_out);
}

// round 9
// speedup vs baseline: 4.9718x; 1.3133x over previous
#include <cuda_runtime.h>
#include <cuda_fp16.h>
#include <cstddef>

// Problem constants
#define B_TOT   16384
#define T_STEPS 128
#define F_IN    12
#define H1      64
#define H2      128
#define BT      32
#define NTH     256
#define GRID    (B_TOT / BT)   // 512

// A-buffer geometry (single fp16 plane in smem), stride 408:
// cols [0,16)=x, [16,80)=h0 parity0, [80,144)=h0 parity1,
//      [144,272)=h1 parity0, [272,400)=h1 parity1
#define H0B     16
#define H1B     144
#define ASTRIDE 408

// ---------------------------------------------------------------------------
// Device-global scratch (weights only; ~480KB)
// ---------------------------------------------------------------------------
__device__ uint4 g_WfragL0[5 * 32 * 32];    // [kt][nt][lane] -> (bh0,bh1,bl0,bl1) fp16x2
__device__ uint4 g_WfragL1[12 * 64 * 32];
__device__ float g_b0i[256];                // gate-interleaved biases: col = 4u+g
__device__ float g_b1i[512];

// ---------------------------------------------------------------------------
// Helpers
// ---------------------------------------------------------------------------
__device__ __forceinline__ unsigned pack_h2(float a, float b) {
    __half2 t = __floats2half2_rn(a, b);    // .x = a (low half), .y = b (high half)
    unsigned r; memcpy(&r, &t, 4); return r;
}
__device__ __forceinline__ float sigm(float x) {
    return __fdividef(1.0f, 1.0f + __expf(-x));
}
__device__ __forceinline__ float tanh_f(float x) {
    return 1.0f - __fdividef(2.0f, 1.0f + __expf(2.0f * x));
}

__device__ __forceinline__ void mma16816(float* d, const unsigned* a, unsigned b0, unsigned b1) {
    asm volatile(
        "mma.sync.aligned.m16n8k16.row.col.f32.f16.f16.f32 "
        "{%0,%1,%2,%3}, {%4,%5,%6,%7}, {%8,%9}, {%0,%1,%2,%3};\n"
        : "+f"(d[0]), "+f"(d[1]), "+f"(d[2]), "+f"(d[3])
        : "r"(a[0]), "r"(a[1]), "r"(a[2]), "r"(a[3]), "r"(b0), "r"(b1));
}

// A fragment (m16k16, row-major): a0=[r][c..c+1] a1=[r+8][c..] a2=[r][c+8..] a3=[r+8][c+8..]
__device__ __forceinline__ void ldA(unsigned* a, const __half* plane, int row0, int colbase) {
    a[0] = *(const unsigned*)&plane[row0 * ASTRIDE + colbase];
    a[1] = *(const unsigned*)&plane[(row0 + 8) * ASTRIDE + colbase];
    a[2] = *(const unsigned*)&plane[row0 * ASTRIDE + colbase + 8];
    a[3] = *(const unsigned*)&plane[(row0 + 8) * ASTRIDE + colbase + 8];
}

// ---------------------------------------------------------------------------
// Repack: weights -> mma B-fragment order (fp16 hi/lo), gate-interleaved (col=4u+g)
// B frag (k16 x n8, "col"): lane t, reg r, half h -> k = (t%4)*2 + r*8 + h, n = t/4
// ---------------------------------------------------------------------------
__global__ void repack(const float* __restrict__ W_ih0, const float* __restrict__ W_hh0,
                       const float* __restrict__ b_ih0, const float* __restrict__ b_hh0,
                       const float* __restrict__ W_ih1, const float* __restrict__ W_hh1,
                       const float* __restrict__ b_ih1, const float* __restrict__ b_hh1)
{
    const int T0 = 5 * 32 * 32, T1 = 12 * 64 * 32;
    for (int idx = blockIdx.x * blockDim.x + threadIdx.x;
         idx < T0 + T1 + 256 + 512; idx += gridDim.x * blockDim.x) {
        if (idx < T0 + T1) {
            int lidx = idx, isL1 = 0;
            if (lidx >= T0) { lidx -= T0; isL1 = 1; }
            int lane = lidx & 31;
            int ntcnt = isL1 ? 64 : 32;
            int nt = (lidx >> 5) % ntcnt;
            int kt = (lidx >> 5) / ntcnt;
            int n = nt * 8 + (lane >> 2);
            float v[4];
            #pragma unroll
            for (int q = 0; q < 4; q++) {
                int k = kt * 16 + (lane & 3) * 2 + (q >> 1) * 8 + (q & 1);
                float val;
                if (!isL1) {
                    int row = (n & 3) * H1 + (n >> 2);
                    if (k < 16) val = (k < F_IN) ? W_ih0[row * F_IN + k] : 0.0f;
                    else        val = W_hh0[row * H1 + (k - 16)];
                } else {
                    int row = (n & 3) * H2 + (n >> 2);
                    if (k < 64) val = W_ih1[row * H1 + k];
                    else        val = W_hh1[row * H2 + (k - 64)];
                }
                v[q] = val;
            }
            float hi[4], lo[4];
            #pragma unroll
            for (int q = 0; q < 4; q++) {
                __half h = __float2half_rn(v[q]);
                hi[q] = __half2float(h);
                lo[q] = v[q] - hi[q];
            }
            uint4 w;
            w.x = pack_h2(hi[0], hi[1]);   // Bh reg0
            w.y = pack_h2(hi[2], hi[3]);   // Bh reg1
            w.z = pack_h2(lo[0], lo[1]);   // Bl reg0
            w.w = pack_h2(lo[2], lo[3]);   // Bl reg1
            if (!isL1) g_WfragL0[(kt * 32 + nt) * 32 + lane] = w;
            else       g_WfragL1[(kt * 64 + nt) * 32 + lane] = w;
        } else if (idx < T0 + T1 + 256) {
            int n = idx - (T0 + T1);
            int row = (n & 3) * H1 + (n >> 2);
            g_b0i[n] = b_ih0[row] + b_hh0[row];
        } else {
            int n = idx - (T0 + T1 + 256);
            int row = (n & 3) * H2 + (n >> 2);
            g_b1i[n] = b_ih1[row] + b_hh1[row];
        }
    }
}

// ---------------------------------------------------------------------------
// Main kernel: BT=32 batch/block, 8 warps = (mt 0..1) x (ng 0..3), 2 blocks/SM.
// h0/h1 double-buffered by column parity -> 2 __syncthreads per step.
// 2-term fp16 split MMA (weights hi+lo, activations single fp16), fp32 accum.
// ---------------------------------------------------------------------------
__global__ __launch_bounds__(NTH, 2) void lstm_mma(
    const float* __restrict__ xin,
    const float* __restrict__ Wd1, const float* __restrict__ bd1,
    const float* __restrict__ Wd2, const float* __restrict__ bd2,
    float* __restrict__ out)
{
    extern __shared__ unsigned char smraw[];
    __half* As   = (__half*)smraw;                                 // 32*408 fp16
    float* bias0 = (float*)(smraw + (size_t)BT * ASTRIDE * 2);     // 256
    float* bias1 = bias0 + 256;                                    // 512
    float* csm   = bias1 + 512;                                    // 24*256

    const int tid  = threadIdx.x;
    const int wid  = tid >> 5, lane = tid & 31;
    const int mt   = wid & 1, ng = wid >> 1;
    const int grp  = lane >> 2;          // 0..7
    const int qc   = lane & 3;           // 0..3
    const int par  = lane & 1;
    const int row0 = mt * 16 + grp;
    const int ebase = blockIdx.x * BT;

    // init smem
    for (int i = tid; i < 256; i += NTH) bias0[i] = g_b0i[i];
    for (int i = tid; i < 512; i += NTH) bias1[i] = g_b1i[i];
    for (int i = tid; i < 24 * 256; i += NTH) csm[i] = 0.0f;
    for (int i = tid; i < BT * ASTRIDE; i += NTH)
        ((unsigned short*)As)[i] = 0;    // +0.0 fp16
    __syncthreads();

    for (int t = 0; t < T_STEPS; t++) {
        const int h0r = H0B + (t & 1) * 64;          // read-parity h0
        const int h0w = H0B + ((t + 1) & 1) * 64;    // write-parity h0
        const int h1r = H1B + (t & 1) * 128;
        const int h1w = H1B + ((t + 1) & 1) * 128;

        // ---- stage x_t (32 rows x 16 cols fp16, 2 vals/thread) ----
        #pragma unroll
        for (int i = 0; i < 2; i++) {
            int idx = tid + i * NTH;                 // 0..511
            int r = idx >> 4, c = idx & 15;
            float v = 0.0f;
            if (c < F_IN)
                v = xin[((size_t)(ebase + r) * T_STEPS + t) * F_IN + c];
            As[r * ASTRIDE + c] = __float2half_rn(v);
        }
        __syncthreads();   // x + h0/h1[new from t-1] visible

        // ================= Layer 0 GEMM: K=80 = x(16) || h0_old(64) ========
        float d0[8][4];
        #pragma unroll
        for (int j = 0; j < 8; j++) {
            float2 b = *(const float2*)&bias0[ng * 64 + j * 8 + qc * 2];
            d0[j][0] = b.x; d0[j][1] = b.y; d0[j][2] = b.x; d0[j][3] = b.y;
        }
        #pragma unroll
        for (int kt = 0; kt < 5; kt++) {
            int colbase = (kt == 0) ? (qc * 2) : (h0r + (kt - 1) * 16 + qc * 2);
            unsigned ah[4];
            ldA(ah, As, row0, colbase);
            #pragma unroll
            for (int j = 0; j < 8; j++) {
                uint4 w = g_WfragL0[(kt * 32 + ng * 8 + j) * 32 + lane];
                mma16816(d0[j], ah, w.x, w.y);   // A*Bh
                mma16816(d0[j], ah, w.z, w.w);   // A*Bl
            }
        }

        // ---- L0 elementwise -> h0[write parity] ----
        #pragma unroll
        for (int j = 0; j < 8; j++) {
            float s0 = par ? d0[j][0] : d0[j][2];
            float s1 = par ? d0[j][1] : d0[j][3];
            float v0 = __shfl_xor_sync(0xffffffffu, s0, 1);
            float v1 = __shfl_xor_sync(0xffffffffu, s1, 1);
            float zi, zf, zg, zo;
            if (par == 0) { zi = d0[j][0]; zf = d0[j][1]; zg = v0; zo = v1; }
            else          { zi = v0; zf = v1; zg = d0[j][2]; zo = d0[j][3]; }
            float c = csm[j * 256 + tid];
            c = fmaf(sigm(zf), c, sigm(zi) * tanh_f(zg));
            csm[j * 256 + tid] = c;
            float h = sigm(zo) * tanh_f(c);
            int u  = ng * 16 + j * 2 + (qc >> 1);
            int rr = row0 + (par ? 8 : 0);
            As[rr * ASTRIDE + h0w + u] = __float2half_rn(h);
        }
        __syncthreads();   // h0[new] complete

        // ================= Layer 1 GEMM: K=192 = h0_new(64) || h1_old(128) ==
        float d1[16][4];
        #pragma unroll
        for (int j = 0; j < 16; j++) {
            float2 b = *(const float2*)&bias1[ng * 128 + j * 8 + qc * 2];
            d1[j][0] = b.x; d1[j][1] = b.y; d1[j][2] = b.x; d1[j][3] = b.y;
        }
        #pragma unroll
        for (int kt = 0; kt < 12; kt++) {
            int colbase = (kt < 4) ? (h0w + kt * 16 + qc * 2)
                                   : (h1r + (kt - 4) * 16 + qc * 2);
            unsigned ah[4];
            ldA(ah, As, row0, colbase);
            #pragma unroll
            for (int j = 0; j < 16; j++) {
                uint4 w = g_WfragL1[(kt * 64 + ng * 16 + j) * 32 + lane];
                mma16816(d1[j], ah, w.x, w.y);
                mma16816(d1[j], ah, w.z, w.w);
            }
        }

        // ---- L1 elementwise -> h1[write parity] (next step's barrier covers) ----
        #pragma unroll
        for (int j = 0; j < 16; j++) {
            float s0 = par ? d1[j][0] : d1[j][2];
            float s1 = par ? d1[j][1] : d1[j][3];
            float v0 = __shfl_xor_sync(0xffffffffu, s0, 1);
            float v1 = __shfl_xor_sync(0xffffffffu, s1, 1);
            float zi, zf, zg, zo;
            if (par == 0) { zi = d1[j][0]; zf = d1[j][1]; zg = v0; zo = v1; }
            else          { zi = v0; zf = v1; zg = d1[j][2]; zo = d1[j][3]; }
            float c = csm[(8 + j) * 256 + tid];
            c = fmaf(sigm(zf), c, sigm(zi) * tanh_f(zg));
            csm[(8 + j) * 256 + tid] = c;
            float h = sigm(zo) * tanh_f(c);
            int u  = ng * 32 + j * 2 + (qc >> 1);
            int rr = row0 + (par ? 8 : 0);
            As[rr * ASTRIDE + h1w + u] = __float2half_rn(h);
        }
    }
    __syncthreads();   // final h1 (parity 0 at H1B) visible block-wide

    // ================= Dense head =================
    {
        int e = tid >> 3, q = tid & 7;      // 32 elems x 8 partials
        float s = 0.0f;
        for (int m = q * 8; m < q * 8 + 8; m++) {
            float dsum = bd1[m];
            #pragma unroll 4
            for (int jj = 0; jj < H2; jj++) {
                float hv = __half2float(As[e * ASTRIDE + H1B + jj]);
                dsum = fmaf(Wd1[m * H2 + jj], hv, dsum);
            }
            s = fmaf(Wd2[m], dsum, s);
        }
        csm[tid] = s;
        __syncthreads();
        if (q == 0) {
            float r = 0.0f;
            #pragma unroll
            for (int k = 0; k < 8; k++) r += csm[e * 8 + k];
            out[ebase + e] = r + bd2[0];
        }
    }
}

// ---------------------------------------------------------------------------
// Launch
// ---------------------------------------------------------------------------
extern "C" void kernel_launch(void* const* d_in, const int* in_sizes, int n_in,
                              void* d_out, int out_size)
{
    (void)in_sizes; (void)n_in; (void)out_size;
    const float* input_seq = (const float*)d_in[0];
    const float* W_ih0 = (const float*)d_in[1];
    const float* W_hh0 = (const float*)d_in[2];
    const float* b_ih0 = (const float*)d_in[3];
    const float* b_hh0 = (const float*)d_in[4];
    const float* W_ih1 = (const float*)d_in[5];
    const float* W_hh1 = (const float*)d_in[6];
    const float* b_ih1 = (const float*)d_in[7];
    const float* b_hh1 = (const float*)d_in[8];
    const float* W_d1  = (const float*)d_in[9];
    const float* b_d1  = (const float*)d_in[10];
    const float* W_d2  = (const float*)d_in[11];
    const float* b_d2  = (const float*)d_in[12];

    const size_t smem_bytes = (size_t)BT * ASTRIDE * 2          // A plane (26112)
                            + (256 + 512) * sizeof(float)       // biases  (3072)
                            + 24 * 256 * sizeof(float);         // c state (24576)
    cudaFuncSetAttribute(lstm_mma, cudaFuncAttributeMaxDynamicSharedMemorySize, (int)smem_bytes);

    repack<<<128, 256>>>(W_ih0, W_hh0, b_ih0, b_hh0, W_ih1, W_hh1, b_ih1, b_hh1);
    lstm_mma<<<GRID, NTH, smem_bytes>>>(input_seq, W_d1, b_d1, W_d2, b_d2, (float*)d_out);
}

// round 12
// speedup vs baseline: 5.0859x; 1.0230x over previous
#include <cuda_runtime.h>
#include <cuda_fp16.h>
#include <cstddef>

// Problem constants
#define B_TOT   16384
#define T_STEPS 128
#define F_IN    12
#define H1      64
#define H2      128
#define BT      32
#define NTH     256
#define GRID    (B_TOT / BT)   // 512

// A-buffer geometry (single fp16 plane in smem), stride 424:
// cols [0,16)=x par0, [16,32)=x par1, [32,96)=h0 par0, [96,160)=h0 par1,
//      [160,288)=h1 par0, [288,416)=h1 par1
#define XB      0
#define H0B     32
#define H1B     160
#define ASTRIDE 424

// ---------------------------------------------------------------------------
// Device-global scratch (weights only; ~480KB)
// ---------------------------------------------------------------------------
__device__ uint4 g_WfragL0[5 * 32 * 32];    // [kt][nt][lane] -> (bh0,bh1,bl0,bl1) fp16x2
__device__ uint4 g_WfragL1[12 * 64 * 32];
__device__ float g_b0i[256];                // gate-interleaved biases: col = 4u+g
__device__ float g_b1i[512];

// ---------------------------------------------------------------------------
// Helpers
// ---------------------------------------------------------------------------
__device__ __forceinline__ unsigned pack_h2(float a, float b) {
    __half2 t = __floats2half2_rn(a, b);
    unsigned r; memcpy(&r, &t, 4); return r;
}
__device__ __forceinline__ float sigm(float x) {
    return __fdividef(1.0f, 1.0f + __expf(-x));
}
__device__ __forceinline__ float tanh_f(float x) {
    return 1.0f - __fdividef(2.0f, 1.0f + __expf(2.0f * x));
}

__device__ __forceinline__ void mma16816(float* d, const unsigned* a, unsigned b0, unsigned b1) {
    asm volatile(
        "mma.sync.aligned.m16n8k16.row.col.f32.f16.f16.f32 "
        "{%0,%1,%2,%3}, {%4,%5,%6,%7}, {%8,%9}, {%0,%1,%2,%3};\n"
        : "+f"(d[0]), "+f"(d[1]), "+f"(d[2]), "+f"(d[3])
        : "r"(a[0]), "r"(a[1]), "r"(a[2]), "r"(a[3]), "r"(b0), "r"(b1));
}

// A fragment (m16k16, row-major): a0=[r][c..c+1] a1=[r+8][c..] a2=[r][c+8..] a3=[r+8][c+8..]
__device__ __forceinline__ void ldA(unsigned* a, const __half* plane, int row0, int colbase) {
    a[0] = *(const unsigned*)&plane[row0 * ASTRIDE + colbase];
    a[1] = *(const unsigned*)&plane[(row0 + 8) * ASTRIDE + colbase];
    a[2] = *(const unsigned*)&plane[row0 * ASTRIDE + colbase + 8];
    a[3] = *(const unsigned*)&plane[(row0 + 8) * ASTRIDE + colbase + 8];
}

// ---------------------------------------------------------------------------
// Repack: weights -> mma B-fragment order (fp16 hi/lo), gate-interleaved (col=4u+g)
// B frag (k16 x n8, "col"): lane t, reg r, half h -> k = (t%4)*2 + r*8 + h, n = t/4
// ---------------------------------------------------------------------------
__global__ void repack(const float* __restrict__ W_ih0, const float* __restrict__ W_hh0,
                       const float* __restrict__ b_ih0, const float* __restrict__ b_hh0,
                       const float* __restrict__ W_ih1, const float* __restrict__ W_hh1,
                       const float* __restrict__ b_ih1, const float* __restrict__ b_hh1)
{
    const int T0 = 5 * 32 * 32, T1 = 12 * 64 * 32;
    for (int idx = blockIdx.x * blockDim.x + threadIdx.x;
         idx < T0 + T1 + 256 + 512; idx += gridDim.x * blockDim.x) {
        if (idx < T0 + T1) {
            int lidx = idx, isL1 = 0;
            if (lidx >= T0) { lidx -= T0; isL1 = 1; }
            int lane = lidx & 31;
            int ntcnt = isL1 ? 64 : 32;
            int nt = (lidx >> 5) % ntcnt;
            int kt = (lidx >> 5) / ntcnt;
            int n = nt * 8 + (lane >> 2);
            float v[4];
            #pragma unroll
            for (int q = 0; q < 4; q++) {
                int k = kt * 16 + (lane & 3) * 2 + (q >> 1) * 8 + (q & 1);
                float val;
                if (!isL1) {
                    int row = (n & 3) * H1 + (n >> 2);
                    if (k < 16) val = (k < F_IN) ? W_ih0[row * F_IN + k] : 0.0f;
                    else        val = W_hh0[row * H1 + (k - 16)];
                } else {
                    int row = (n & 3) * H2 + (n >> 2);
                    if (k < 64) val = W_ih1[row * H1 + k];
                    else        val = W_hh1[row * H2 + (k - 64)];
                }
                v[q] = val;
            }
            float hi[4], lo[4];
            #pragma unroll
            for (int q = 0; q < 4; q++) {
                __half h = __float2half_rn(v[q]);
                hi[q] = __half2float(h);
                lo[q] = v[q] - hi[q];
            }
            uint4 w;
            w.x = pack_h2(hi[0], hi[1]);   // Bh reg0
            w.y = pack_h2(hi[2], hi[3]);   // Bh reg1
            w.z = pack_h2(lo[0], lo[1]);   // Bl reg0
            w.w = pack_h2(lo[2], lo[3]);   // Bl reg1
            if (!isL1) g_WfragL0[(kt * 32 + nt) * 32 + lane] = w;
            else       g_WfragL1[(kt * 64 + nt) * 32 + lane] = w;
        } else if (idx < T0 + T1 + 256) {
            int n = idx - (T0 + T1);
            int row = (n & 3) * H1 + (n >> 2);
            g_b0i[n] = b_ih0[row] + b_hh0[row];
        } else {
            int n = idx - (T0 + T1 + 256);
            int row = (n & 3) * H2 + (n >> 2);
            g_b1i[n] = b_ih1[row] + b_hh1[row];
        }
    }
}

// ---------------------------------------------------------------------------
// Main kernel: BT=32/block, 8 warps = (mt 0..1) x (ng 0..3), 2 blocks/SM.
// Per step: Phase A = L0 GEMM -> L0 EW (d0 dies) -> L1 h1-part GEMM (kt4..11);
//           barrier; Phase B = L1 h0-part GEMM (kt0..3) + x(t+1) stage + L1 EW.
// Sequential accumulator liveness (max 64 fp32) keeps regalloc at R9 levels.
// x/h0/h1 all double-buffered by parity -> 2 __syncthreads per step.
// 2-term fp16 split MMA (weights hi+lo, activations single fp16), fp32 accum.
// ---------------------------------------------------------------------------
__global__ __launch_bounds__(NTH, 2) void lstm_mma(
    const float* __restrict__ xin,
    const float* __restrict__ Wd1, const float* __restrict__ bd1,
    const float* __restrict__ Wd2, const float* __restrict__ bd2,
    float* __restrict__ out)
{
    extern __shared__ unsigned char smraw[];
    __half* As   = (__half*)smraw;                                 // 32*424 fp16
    float* bias0 = (float*)(smraw + (size_t)BT * ASTRIDE * 2);     // 256
    float* bias1 = bias0 + 256;                                    // 512
    float* csm   = bias1 + 512;                                    // 24*256

    const int tid  = threadIdx.x;
    const int wid  = tid >> 5, lane = tid & 31;
    const int mt   = wid & 1, ng = wid >> 1;
    const int grp  = lane >> 2;          // 0..7
    const int qc   = lane & 3;           // 0..3
    const int par  = lane & 1;
    const int row0 = mt * 16 + grp;
    const int ebase = blockIdx.x * BT;

    // init smem
    for (int i = tid; i < 256; i += NTH) bias0[i] = g_b0i[i];
    for (int i = tid; i < 512; i += NTH) bias1[i] = g_b1i[i];
    for (int i = tid; i < 24 * 256; i += NTH) csm[i] = 0.0f;
    for (int i = tid; i < BT * ASTRIDE; i += NTH)
        ((unsigned short*)As)[i] = 0;    // +0.0 fp16
    __syncthreads();

    // prologue: stage x(t=0) into x parity 0
    #pragma unroll
    for (int i = 0; i < 2; i++) {
        int idx = tid + i * NTH;
        int r = idx >> 4, c = idx & 15;
        float v = (c < F_IN) ? xin[((size_t)(ebase + r) * T_STEPS + 0) * F_IN + c] : 0.0f;
        As[r * ASTRIDE + XB + c] = __float2half_rn(v);
    }

    for (int t = 0; t < T_STEPS; t++) {
        const int xr0 = XB  + (t & 1) * 16;          // x(t)
        const int xw0 = XB  + ((t + 1) & 1) * 16;    // x(t+1) staging
        const int h0r = H0B + (t & 1) * 64;
        const int h0w = H0B + ((t + 1) & 1) * 64;
        const int h1r = H1B + (t & 1) * 128;
        const int h1w = H1B + ((t + 1) & 1) * 128;

        __syncthreads();   // x(t), h0(t), h1(t) visible

        // ========== Phase A1: L0 GEMM (K=80 = x(16) || h0_old(64)) ==========
        {
            float d0[8][4];
            #pragma unroll
            for (int j = 0; j < 8; j++) {
                float2 b = *(const float2*)&bias0[ng * 64 + j * 8 + qc * 2];
                d0[j][0] = b.x; d0[j][1] = b.y; d0[j][2] = b.x; d0[j][3] = b.y;
            }
            #pragma unroll
            for (int kt = 0; kt < 5; kt++) {
                int colbase = (kt == 0) ? (xr0 + qc * 2) : (h0r + (kt - 1) * 16 + qc * 2);
                unsigned ah[4];
                ldA(ah, As, row0, colbase);
                #pragma unroll
                for (int j = 0; j < 8; j++) {
                    uint4 w = g_WfragL0[(kt * 32 + ng * 8 + j) * 32 + lane];
                    mma16816(d0[j], ah, w.x, w.y);   // A*Bh
                    mma16816(d0[j], ah, w.z, w.w);   // A*Bl
                }
            }

            // ---- L0 elementwise -> h0[write parity] (d0 dies here) ----
            #pragma unroll
            for (int j = 0; j < 8; j++) {
                float s0 = par ? d0[j][0] : d0[j][2];
                float s1 = par ? d0[j][1] : d0[j][3];
                float v0 = __shfl_xor_sync(0xffffffffu, s0, 1);
                float v1 = __shfl_xor_sync(0xffffffffu, s1, 1);
                float zi, zf, zg, zo;
                if (par == 0) { zi = d0[j][0]; zf = d0[j][1]; zg = v0; zo = v1; }
                else          { zi = v0; zf = v1; zg = d0[j][2]; zo = d0[j][3]; }
                float c = csm[j * 256 + tid];
                c = fmaf(sigm(zf), c, sigm(zi) * tanh_f(zg));
                csm[j * 256 + tid] = c;
                float h = sigm(zo) * tanh_f(c);
                int u  = ng * 16 + j * 2 + (qc >> 1);
                int rr = row0 + (par ? 8 : 0);
                As[rr * ASTRIDE + h0w + u] = __float2half_rn(h);
            }
        }

        // ========== Phase A2: L1 h1-recurrent part (kt 4..11) ==========
        float d1[16][4];
        #pragma unroll
        for (int j = 0; j < 16; j++) {
            float2 b = *(const float2*)&bias1[ng * 128 + j * 8 + qc * 2];
            d1[j][0] = b.x; d1[j][1] = b.y; d1[j][2] = b.x; d1[j][3] = b.y;
        }
        #pragma unroll
        for (int kt = 4; kt < 12; kt++) {          // h1_old part (independent of h0_new)
            int colbase = h1r + (kt - 4) * 16 + qc * 2;
            unsigned ah[4];
            ldA(ah, As, row0, colbase);
            #pragma unroll
            for (int j = 0; j < 16; j++) {
                uint4 w = g_WfragL1[(kt * 64 + ng * 16 + j) * 32 + lane];
                mma16816(d1[j], ah, w.x, w.y);
                mma16816(d1[j], ah, w.z, w.w);
            }
        }
        __syncthreads();   // h0[new] complete block-wide

        // ========== Phase B: L1 h0-part (kt 0..3) + x(t+1) stage + L1 EW ====
        // issue x(t+1) global loads early; store to smem after the MMAs
        float xv[2];
        if (t + 1 < T_STEPS) {
            #pragma unroll
            for (int i = 0; i < 2; i++) {
                int idx = tid + i * NTH;
                int r = idx >> 4, c = idx & 15;
                xv[i] = (c < F_IN)
                    ? xin[((size_t)(ebase + r) * T_STEPS + (t + 1)) * F_IN + c] : 0.0f;
            }
        }

        #pragma unroll
        for (int kt = 0; kt < 4; kt++) {           // h0_new part
            int colbase = h0w + kt * 16 + qc * 2;
            unsigned ah[4];
            ldA(ah, As, row0, colbase);
            #pragma unroll
            for (int j = 0; j < 16; j++) {
                uint4 w = g_WfragL1[(kt * 64 + ng * 16 + j) * 32 + lane];
                mma16816(d1[j], ah, w.x, w.y);
                mma16816(d1[j], ah, w.z, w.w);
            }
        }

        if (t + 1 < T_STEPS) {
            #pragma unroll
            for (int i = 0; i < 2; i++) {
                int idx = tid + i * NTH;
                int r = idx >> 4, c = idx & 15;
                As[r * ASTRIDE + xw0 + c] = __float2half_rn(xv[i]);
            }
        }

        // ---- L1 elementwise -> h1[write parity] (next step's barrier covers) ----
        #pragma unroll
        for (int j = 0; j < 16; j++) {
            float s0 = par ? d1[j][0] : d1[j][2];
            float s1 = par ? d1[j][1] : d1[j][3];
            float v0 = __shfl_xor_sync(0xffffffffu, s0, 1);
            float v1 = __shfl_xor_sync(0xffffffffu, s1, 1);
            float zi, zf, zg, zo;
            if (par == 0) { zi = d1[j][0]; zf = d1[j][1]; zg = v0; zo = v1; }
            else          { zi = v0; zf = v1; zg = d1[j][2]; zo = d1[j][3]; }
            float c = csm[(8 + j) * 256 + tid];
            c = fmaf(sigm(zf), c, sigm(zi) * tanh_f(zg));
            csm[(8 + j) * 256 + tid] = c;
            float h = sigm(zo) * tanh_f(c);
            int u  = ng * 32 + j * 2 + (qc >> 1);
            int rr = row0 + (par ? 8 : 0);
            As[rr * ASTRIDE + h1w + u] = __float2half_rn(h);
        }
    }
    __syncthreads();   // final h1 (parity 0 at H1B) visible block-wide

    // ================= Dense head =================
    {
        int e = tid >> 3, q = tid & 7;      // 32 elems x 8 partials
        float s = 0.0f;
        for (int m = q * 8; m < q * 8 + 8; m++) {
            float dsum = bd1[m];
            #pragma unroll 4
            for (int jj = 0; jj < H2; jj++) {
                float hv = __half2float(As[e * ASTRIDE + H1B + jj]);
                dsum = fmaf(Wd1[m * H2 + jj], hv, dsum);
            }
            s = fmaf(Wd2[m], dsum, s);
        }
        csm[tid] = s;
        __syncthreads();
        if (q == 0) {
            float r = 0.0f;
            #pragma unroll
            for (int k = 0; k < 8; k++) r += csm[e * 8 + k];
            out[ebase + e] = r + bd2[0];
        }
    }
}

// ---------------------------------------------------------------------------
// Launch
// ---------------------------------------------------------------------------
extern "C" void kernel_launch(void* const* d_in, const int* in_sizes, int n_in,
                              void* d_out, int out_size)
{
    (void)in_sizes; (void)n_in; (void)out_size;
    const float* input_seq = (const float*)d_in[0];
    const float* W_ih0 = (const float*)d_in[1];
    const float* W_hh0 = (const float*)d_in[2];
    const float* b_ih0 = (const float*)d_in[3];
    const float* b_hh0 = (const float*)d_in[4];
    const float* W_ih1 = (const float*)d_in[5];
    const float* W_hh1 = (const float*)d_in[6];
    const float* b_ih1 = (const float*)d_in[7];
    const float* b_hh1 = (const float*)d_in[8];
    const float* W_d1  = (const float*)d_in[9];
    const float* b_d1  = (const float*)d_in[10];
    const float* W_d2  = (const float*)d_in[11];
    const float* b_d2  = (const float*)d_in[12];

    const size_t smem_bytes = (size_t)BT * ASTRIDE * 2          // A plane (27136)
                            + (256 + 512) * sizeof(float)       // biases  (3072)
                            + 24 * 256 * sizeof(float);         // c state (24576)
    cudaFuncSetAttribute(lstm_mma, cudaFuncAttributeMaxDynamicSharedMemorySize, (int)smem_bytes);

    repack<<<128, 256>>>(W_ih0, W_hh0, b_ih0, b_hh0, W_ih1, W_hh1, b_ih1, b_hh1);
    lstm_mma<<<GRID, NTH, smem_bytes>>>(input_seq, W_d1, b_d1, W_d2, b_d2, (float*)d_out);
}

// round 13
// speedup vs baseline: 5.3502x; 1.0519x over previous
#include <cuda_runtime.h>
#include <cuda_fp16.h>
#include <cstddef>

// Problem constants
#define B_TOT   16384
#define T_STEPS 128
#define F_IN    12
#define H1      64
#define H2      128
#define BT      32
#define NTH     256
#define GRID    (B_TOT / BT)   // 512

// A-buffer geometry (single fp16 plane in smem), stride 424:
// cols [0,16)=x par0, [16,32)=x par1, [32,96)=h0 par0, [96,160)=h0 par1,
//      [160,288)=h1 par0, [288,416)=h1 par1
#define XB      0
#define H0B     32
#define H1B     160
#define ASTRIDE 424

// ---------------------------------------------------------------------------
// Device-global scratch (weights only; ~480KB)
// ---------------------------------------------------------------------------
__device__ uint4 g_WfragL0[5 * 32 * 32];    // [kt][nt][lane] -> (bh0,bh1,bl0,bl1) fp16x2
__device__ uint4 g_WfragL1[12 * 64 * 32];
__device__ float g_b0i[256];                // gate-interleaved biases: col = 4u+g
__device__ float g_b1i[512];

// ---------------------------------------------------------------------------
// Helpers
// ---------------------------------------------------------------------------
__device__ __forceinline__ unsigned pack_h2(float a, float b) {
    __half2 t = __floats2half2_rn(a, b);
    unsigned r; memcpy(&r, &t, 4); return r;
}
__device__ __forceinline__ float sigm(float x) {
    return __fdividef(1.0f, 1.0f + __expf(-x));
}
__device__ __forceinline__ float tanh_f(float x) {
    return 1.0f - __fdividef(2.0f, 1.0f + __expf(2.0f * x));
}

__device__ __forceinline__ void mma16816(float* d, const unsigned* a, unsigned b0, unsigned b1) {
    asm volatile(
        "mma.sync.aligned.m16n8k16.row.col.f32.f16.f16.f32 "
        "{%0,%1,%2,%3}, {%4,%5,%6,%7}, {%8,%9}, {%0,%1,%2,%3};\n"
        : "+f"(d[0]), "+f"(d[1]), "+f"(d[2]), "+f"(d[3])
        : "r"(a[0]), "r"(a[1]), "r"(a[2]), "r"(a[3]), "r"(b0), "r"(b1));
}

// A fragment (m16k16, row-major): a0=[r][c..c+1] a1=[r+8][c..] a2=[r][c+8..] a3=[r+8][c+8..]
__device__ __forceinline__ void ldA(unsigned* a, const __half* plane, int row0, int colbase) {
    a[0] = *(const unsigned*)&plane[row0 * ASTRIDE + colbase];
    a[1] = *(const unsigned*)&plane[(row0 + 8) * ASTRIDE + colbase];
    a[2] = *(const unsigned*)&plane[row0 * ASTRIDE + colbase + 8];
    a[3] = *(const unsigned*)&plane[(row0 + 8) * ASTRIDE + colbase + 8];
}

// ---------------------------------------------------------------------------
// Repack: weights -> mma B-fragment order (fp16 hi/lo), gate-interleaved (col=4u+g)
// B frag (k16 x n8, "col"): lane t, reg r, half h -> k = (t%4)*2 + r*8 + h, n = t/4
// (unchanged layout; main kernel just decomposes nt differently)
// ---------------------------------------------------------------------------
__global__ void repack(const float* __restrict__ W_ih0, const float* __restrict__ W_hh0,
                       const float* __restrict__ b_ih0, const float* __restrict__ b_hh0,
                       const float* __restrict__ W_ih1, const float* __restrict__ W_hh1,
                       const float* __restrict__ b_ih1, const float* __restrict__ b_hh1)
{
    const int T0 = 5 * 32 * 32, T1 = 12 * 64 * 32;
    for (int idx = blockIdx.x * blockDim.x + threadIdx.x;
         idx < T0 + T1 + 256 + 512; idx += gridDim.x * blockDim.x) {
        if (idx < T0 + T1) {
            int lidx = idx, isL1 = 0;
            if (lidx >= T0) { lidx -= T0; isL1 = 1; }
            int lane = lidx & 31;
            int ntcnt = isL1 ? 64 : 32;
            int nt = (lidx >> 5) % ntcnt;
            int kt = (lidx >> 5) / ntcnt;
            int n = nt * 8 + (lane >> 2);
            float v[4];
            #pragma unroll
            for (int q = 0; q < 4; q++) {
                int k = kt * 16 + (lane & 3) * 2 + (q >> 1) * 8 + (q & 1);
                float val;
                if (!isL1) {
                    int row = (n & 3) * H1 + (n >> 2);
                    if (k < 16) val = (k < F_IN) ? W_ih0[row * F_IN + k] : 0.0f;
                    else        val = W_hh0[row * H1 + (k - 16)];
                } else {
                    int row = (n & 3) * H2 + (n >> 2);
                    if (k < 64) val = W_ih1[row * H1 + k];
                    else        val = W_hh1[row * H2 + (k - 64)];
                }
                v[q] = val;
            }
            float hi[4], lo[4];
            #pragma unroll
            for (int q = 0; q < 4; q++) {
                __half h = __float2half_rn(v[q]);
                hi[q] = __half2float(h);
                lo[q] = v[q] - hi[q];
            }
            uint4 w;
            w.x = pack_h2(hi[0], hi[1]);   // Bh reg0
            w.y = pack_h2(hi[2], hi[3]);   // Bh reg1
            w.z = pack_h2(lo[0], lo[1]);   // Bl reg0
            w.w = pack_h2(lo[2], lo[3]);   // Bl reg1
            if (!isL1) g_WfragL0[(kt * 32 + nt) * 32 + lane] = w;
            else       g_WfragL1[(kt * 64 + nt) * 32 + lane] = w;
        } else if (idx < T0 + T1 + 256) {
            int n = idx - (T0 + T1);
            int row = (n & 3) * H1 + (n >> 2);
            g_b0i[n] = b_ih0[row] + b_hh0[row];
        } else {
            int n = idx - (T0 + T1 + 256);
            int row = (n & 3) * H2 + (n >> 2);
            g_b1i[n] = b_ih1[row] + b_hh1[row];
        }
    }
}

// ---------------------------------------------------------------------------
// Main kernel: BT=32/block, 8 warps = ng 0..7, each warp M=32 (2 A-frags),
// N-slice per warp: L0 4 n-tiles, L1 8 n-tiles -> every B-frag load feeds
// 4 MMAs (2 split terms x 2 A frags); weight LDG volume halved vs mt-split.
// Per step: A1 = L0 GEMM + L0 EW; A2 = L1 h1-part (kt4..11); barrier;
//           B = L1 h0-part (kt0..3) + x(t+1) prefetch + L1 EW.
// x/h0/h1 double-buffered by parity -> 2 __syncthreads per step.
// 2-term fp16 split MMA (weights hi+lo, activations single fp16), fp32 accum.
// ---------------------------------------------------------------------------
__global__ __launch_bounds__(NTH, 2) void lstm_mma(
    const float* __restrict__ xin,
    const float* __restrict__ Wd1, const float* __restrict__ bd1,
    const float* __restrict__ Wd2, const float* __restrict__ bd2,
    float* __restrict__ out)
{
    extern __shared__ unsigned char smraw[];
    __half* As   = (__half*)smraw;                                 // 32*424 fp16
    float* bias0 = (float*)(smraw + (size_t)BT * ASTRIDE * 2);     // 256
    float* bias1 = bias0 + 256;                                    // 512
    float* csm   = bias1 + 512;                                    // 24*256

    const int tid  = threadIdx.x;
    const int wid  = tid >> 5, lane = tid & 31;
    const int ng   = wid;                // 0..7 n-group
    const int grp  = lane >> 2;          // 0..7
    const int qc   = lane & 3;           // 0..3
    const int par  = lane & 1;
    const int ebase = blockIdx.x * BT;

    // init smem
    for (int i = tid; i < 256; i += NTH) bias0[i] = g_b0i[i];
    for (int i = tid; i < 512; i += NTH) bias1[i] = g_b1i[i];
    for (int i = tid; i < 24 * 256; i += NTH) csm[i] = 0.0f;
    for (int i = tid; i < BT * ASTRIDE; i += NTH)
        ((unsigned short*)As)[i] = 0;    // +0.0 fp16
    __syncthreads();

    // prologue: stage x(t=0) into x parity 0
    #pragma unroll
    for (int i = 0; i < 2; i++) {
        int idx = tid + i * NTH;
        int r = idx >> 4, c = idx & 15;
        float v = (c < F_IN) ? xin[((size_t)(ebase + r) * T_STEPS + 0) * F_IN + c] : 0.0f;
        As[r * ASTRIDE + XB + c] = __float2half_rn(v);
    }

    for (int t = 0; t < T_STEPS; t++) {
        const int xr0 = XB  + (t & 1) * 16;          // x(t)
        const int xw0 = XB  + ((t + 1) & 1) * 16;    // x(t+1) staging
        const int h0r = H0B + (t & 1) * 64;
        const int h0w = H0B + ((t + 1) & 1) * 64;
        const int h1r = H1B + (t & 1) * 128;
        const int h1w = H1B + ((t + 1) & 1) * 128;

        __syncthreads();   // x(t), h0(t), h1(t) visible

        // ========== Phase A1: L0 GEMM (K=80 = x(16) || h0_old(64)) ==========
        {
            float d0[8][4];   // [j*2+frag]
            #pragma unroll
            for (int j = 0; j < 4; j++) {
                float2 b = *(const float2*)&bias0[(ng * 4 + j) * 8 + qc * 2];
                d0[j*2+0][0] = b.x; d0[j*2+0][1] = b.y; d0[j*2+0][2] = b.x; d0[j*2+0][3] = b.y;
                d0[j*2+1][0] = b.x; d0[j*2+1][1] = b.y; d0[j*2+1][2] = b.x; d0[j*2+1][3] = b.y;
            }
            #pragma unroll
            for (int kt = 0; kt < 5; kt++) {
                int colbase = (kt == 0) ? (xr0 + qc * 2) : (h0r + (kt - 1) * 16 + qc * 2);
                unsigned a0[4], a1[4];
                ldA(a0, As, grp, colbase);        // frag0: rows 0..15
                ldA(a1, As, 16 + grp, colbase);   // frag1: rows 16..31
                #pragma unroll
                for (int j = 0; j < 4; j++) {
                    uint4 w = g_WfragL0[(kt * 32 + ng * 4 + j) * 32 + lane];
                    mma16816(d0[j*2+0], a0, w.x, w.y);
                    mma16816(d0[j*2+0], a0, w.z, w.w);
                    mma16816(d0[j*2+1], a1, w.x, w.y);
                    mma16816(d0[j*2+1], a1, w.z, w.w);
                }
            }

            // ---- L0 elementwise -> h0[write parity] (d0 dies here) ----
            #pragma unroll
            for (int jf = 0; jf < 8; jf++) {
                int j = jf >> 1, f = jf & 1;
                float s0 = par ? d0[jf][0] : d0[jf][2];
                float s1 = par ? d0[jf][1] : d0[jf][3];
                float v0 = __shfl_xor_sync(0xffffffffu, s0, 1);
                float v1 = __shfl_xor_sync(0xffffffffu, s1, 1);
                float zi, zf, zg, zo;
                if (par == 0) { zi = d0[jf][0]; zf = d0[jf][1]; zg = v0; zo = v1; }
                else          { zi = v0; zf = v1; zg = d0[jf][2]; zo = d0[jf][3]; }
                float c = csm[jf * 256 + tid];
                c = fmaf(sigm(zf), c, sigm(zi) * tanh_f(zg));
                csm[jf * 256 + tid] = c;
                float h = sigm(zo) * tanh_f(c);
                int u  = (ng * 4 + j) * 2 + (qc >> 1);
                int rr = f * 16 + grp + (par ? 8 : 0);
                As[rr * ASTRIDE + h0w + u] = __float2half_rn(h);
            }
        }

        // ========== Phase A2: L1 h1-recurrent part (kt 4..11) ==========
        float d1[16][4];   // [j*2+frag]
        #pragma unroll
        for (int j = 0; j < 8; j++) {
            float2 b = *(const float2*)&bias1[(ng * 8 + j) * 8 + qc * 2];
            d1[j*2+0][0] = b.x; d1[j*2+0][1] = b.y; d1[j*2+0][2] = b.x; d1[j*2+0][3] = b.y;
            d1[j*2+1][0] = b.x; d1[j*2+1][1] = b.y; d1[j*2+1][2] = b.x; d1[j*2+1][3] = b.y;
        }
        #pragma unroll
        for (int kt = 4; kt < 12; kt++) {          // h1_old part (independent of h0_new)
            int colbase = h1r + (kt - 4) * 16 + qc * 2;
            unsigned a0[4], a1[4];
            ldA(a0, As, grp, colbase);
            ldA(a1, As, 16 + grp, colbase);
            #pragma unroll
            for (int j = 0; j < 8; j++) {
                uint4 w = g_WfragL1[(kt * 64 + ng * 8 + j) * 32 + lane];
                mma16816(d1[j*2+0], a0, w.x, w.y);
                mma16816(d1[j*2+0], a0, w.z, w.w);
                mma16816(d1[j*2+1], a1, w.x, w.y);
                mma16816(d1[j*2+1], a1, w.z, w.w);
            }
        }
        __syncthreads();   // h0[new] complete block-wide

        // ========== Phase B: L1 h0-part (kt 0..3) + x(t+1) stage + L1 EW ====
        float xv[2];
        if (t + 1 < T_STEPS) {
            #pragma unroll
            for (int i = 0; i < 2; i++) {
                int idx = tid + i * NTH;
                int r = idx >> 4, c = idx & 15;
                xv[i] = (c < F_IN)
                    ? xin[((size_t)(ebase + r) * T_STEPS + (t + 1)) * F_IN + c] : 0.0f;
            }
        }

        #pragma unroll
        for (int kt = 0; kt < 4; kt++) {           // h0_new part
            int colbase = h0w + kt * 16 + qc * 2;
            unsigned a0[4], a1[4];
            ldA(a0, As, grp, colbase);
            ldA(a1, As, 16 + grp, colbase);
            #pragma unroll
            for (int j = 0; j < 8; j++) {
                uint4 w = g_WfragL1[(kt * 64 + ng * 8 + j) * 32 + lane];
                mma16816(d1[j*2+0], a0, w.x, w.y);
                mma16816(d1[j*2+0], a0, w.z, w.w);
                mma16816(d1[j*2+1], a1, w.x, w.y);
                mma16816(d1[j*2+1], a1, w.z, w.w);
            }
        }

        if (t + 1 < T_STEPS) {
            #pragma unroll
            for (int i = 0; i < 2; i++) {
                int idx = tid + i * NTH;
                int r = idx >> 4, c = idx & 15;
                As[r * ASTRIDE + xw0 + c] = __float2half_rn(xv[i]);
            }
        }

        // ---- L1 elementwise -> h1[write parity] (next step's barrier covers) ----
        #pragma unroll
        for (int jf = 0; jf < 16; jf++) {
            int j = jf >> 1, f = jf & 1;
            float s0 = par ? d1[jf][0] : d1[jf][2];
            float s1 = par ? d1[jf][1] : d1[jf][3];
            float v0 = __shfl_xor_sync(0xffffffffu, s0, 1);
            float v1 = __shfl_xor_sync(0xffffffffu, s1, 1);
            float zi, zf, zg, zo;
            if (par == 0) { zi = d1[jf][0]; zf = d1[jf][1]; zg = v0; zo = v1; }
            else          { zi = v0; zf = v1; zg = d1[jf][2]; zo = d1[jf][3]; }
            float c = csm[(8 + jf) * 256 + tid];
            c = fmaf(sigm(zf), c, sigm(zi) * tanh_f(zg));
            csm[(8 + jf) * 256 + tid] = c;
            float h = sigm(zo) * tanh_f(c);
            int u  = (ng * 8 + j) * 2 + (qc >> 1);
            int rr = f * 16 + grp + (par ? 8 : 0);
            As[rr * ASTRIDE + h1w + u] = __float2half_rn(h);
        }
    }
    __syncthreads();   // final h1 (parity 0 at H1B) visible block-wide

    // ================= Dense head =================
    {
        int e = tid >> 3, q = tid & 7;      // 32 elems x 8 partials
        float s = 0.0f;
        for (int m = q * 8; m < q * 8 + 8; m++) {
            float dsum = bd1[m];
            #pragma unroll 4
            for (int jj = 0; jj < H2; jj++) {
                float hv = __half2float(As[e * ASTRIDE + H1B + jj]);
                dsum = fmaf(Wd1[m * H2 + jj], hv, dsum);
            }
            s = fmaf(Wd2[m], dsum, s);
        }
        csm[tid] = s;
        __syncthreads();
        if (q == 0) {
            float r = 0.0f;
            #pragma unroll
            for (int k = 0; k < 8; k++) r += csm[e * 8 + k];
            out[ebase + e] = r + bd2[0];
        }
    }
}

// ---------------------------------------------------------------------------
// Launch
// ---------------------------------------------------------------------------
extern "C" void kernel_launch(void* const* d_in, const int* in_sizes, int n_in,
                              void* d_out, int out_size)
{
    (void)in_sizes; (void)n_in; (void)out_size;
    const float* input_seq = (const float*)d_in[0];
    const float* W_ih0 = (const float*)d_in[1];
    const float* W_hh0 = (const float*)d_in[2];
    const float* b_ih0 = (const float*)d_in[3];
    const float* b_hh0 = (const float*)d_in[4];
    const float* W_ih1 = (const float*)d_in[5];
    const float* W_hh1 = (const float*)d_in[6];
    const float* b_ih1 = (const float*)d_in[7];
    const float* b_hh1 = (const float*)d_in[8];
    const float* W_d1  = (const float*)d_in[9];
    const float* b_d1  = (const float*)d_in[10];
    const float* W_d2  = (const float*)d_in[11];
    const float* b_d2  = (const float*)d_in[12];

    const size_t smem_bytes = (size_t)BT * ASTRIDE * 2          // A plane (27136)
                            + (256 + 512) * sizeof(float)       // biases  (3072)
                            + 24 * 256 * sizeof(float);         // c state (24576)
    cudaFuncSetAttribute(lstm_mma, cudaFuncAttributeMaxDynamicSharedMemorySize, (int)smem_bytes);

    repack<<<128, 256>>>(W_ih0, W_hh0, b_ih0, b_hh0, W_ih1, W_hh1, b_ih1, b_hh1);
    lstm_mma<<<GRID, NTH, smem_bytes>>>(input_seq, W_d1, b_d1, W_d2, b_d2, (float*)d_out);
}

// round 15
// speedup vs baseline: 6.0692x; 1.1344x over previous
#include <cuda_runtime.h>
#include <cuda_fp16.h>
#include <cstddef>

// Problem constants
#define B_TOT   16384
#define T_STEPS 128
#define F_IN    12
#define H1      64
#define H2      128
#define BT      32
#define NTH     256
#define GRID    (B_TOT / BT)   // 512

// A-buffer geometry (single fp16 plane in smem), stride 424:
// cols [0,16)=x par0, [16,32)=x par1, [32,96)=h0 par0, [96,160)=h0 par1,
//      [160,288)=h1 par0, [288,416)=h1 par1
#define XB      0
#define H0B     32
#define H1B     160
#define ASTRIDE 424

// ---------------------------------------------------------------------------
// Device-global scratch (weights only; ~480KB)
// ---------------------------------------------------------------------------
__device__ uint4 g_WfragL0[5 * 32 * 32];    // [kt][nt][lane] -> (bh0,bh1,bl0,bl1) fp16x2
__device__ uint4 g_WfragL1[12 * 64 * 32];
__device__ float g_b0i[256];                // gate-interleaved biases: col = 4u+g
__device__ float g_b1i[512];

// ---------------------------------------------------------------------------
// Helpers
// ---------------------------------------------------------------------------
__device__ __forceinline__ unsigned pack_h2(float a, float b) {
    __half2 t = __floats2half2_rn(a, b);
    unsigned r; memcpy(&r, &t, 4); return r;
}
// HW tanh (MUFU.TANH, sm_75+): 1 MUFU op, rel err ~2^-11
__device__ __forceinline__ float tanh_hw(float x) {
    float r; asm("tanh.approx.f32 %0, %1;" : "=f"(r) : "f"(x)); return r;
}
__device__ __forceinline__ float sigm(float x) {
    return fmaf(0.5f, tanh_hw(0.5f * x), 0.5f);
}

__device__ __forceinline__ void mma16816(float* d, const unsigned* a, unsigned b0, unsigned b1) {
    asm volatile(
        "mma.sync.aligned.m16n8k16.row.col.f32.f16.f16.f32 "
        "{%0,%1,%2,%3}, {%4,%5,%6,%7}, {%8,%9}, {%0,%1,%2,%3};\n"
        : "+f"(d[0]), "+f"(d[1]), "+f"(d[2]), "+f"(d[3])
        : "r"(a[0]), "r"(a[1]), "r"(a[2]), "r"(a[3]), "r"(b0), "r"(b1));
}

// A fragment (m16k16, row-major): a0=[r][c..c+1] a1=[r+8][c..] a2=[r][c+8..] a3=[r+8][c+8..]
__device__ __forceinline__ void ldA(unsigned* a, const __half* plane, int row0, int colbase) {
    a[0] = *(const unsigned*)&plane[row0 * ASTRIDE + colbase];
    a[1] = *(const unsigned*)&plane[(row0 + 8) * ASTRIDE + colbase];
    a[2] = *(const unsigned*)&plane[row0 * ASTRIDE + colbase + 8];
    a[3] = *(const unsigned*)&plane[(row0 + 8) * ASTRIDE + colbase + 8];
}

// ---------------------------------------------------------------------------
// Repack: weights -> mma B-fragment order (fp16 hi/lo), gate-interleaved (col=4u+g)
// B frag (k16 x n8, "col"): lane t, reg r, half h -> k = (t%4)*2 + r*8 + h, n = t/4
// ---------------------------------------------------------------------------
__global__ void repack(const float* __restrict__ W_ih0, const float* __restrict__ W_hh0,
                       const float* __restrict__ b_ih0, const float* __restrict__ b_hh0,
                       const float* __restrict__ W_ih1, const float* __restrict__ W_hh1,
                       const float* __restrict__ b_ih1, const float* __restrict__ b_hh1)
{
    const int T0 = 5 * 32 * 32, T1 = 12 * 64 * 32;
    for (int idx = blockIdx.x * blockDim.x + threadIdx.x;
         idx < T0 + T1 + 256 + 512; idx += gridDim.x * blockDim.x) {
        if (idx < T0 + T1) {
            int lidx = idx, isL1 = 0;
            if (lidx >= T0) { lidx -= T0; isL1 = 1; }
            int lane = lidx & 31;
            int ntcnt = isL1 ? 64 : 32;
            int nt = (lidx >> 5) % ntcnt;
            int kt = (lidx >> 5) / ntcnt;
            int n = nt * 8 + (lane >> 2);
            float v[4];
            #pragma unroll
            for (int q = 0; q < 4; q++) {
                int k = kt * 16 + (lane & 3) * 2 + (q >> 1) * 8 + (q & 1);
                float val;
                if (!isL1) {
                    int row = (n & 3) * H1 + (n >> 2);
                    if (k < 16) val = (k < F_IN) ? W_ih0[row * F_IN + k] : 0.0f;
                    else        val = W_hh0[row * H1 + (k - 16)];
                } else {
                    int row = (n & 3) * H2 + (n >> 2);
                    if (k < 64) val = W_ih1[row * H1 + k];
                    else        val = W_hh1[row * H2 + (k - 64)];
                }
                v[q] = val;
            }
            float hi[4], lo[4];
            #pragma unroll
            for (int q = 0; q < 4; q++) {
                __half h = __float2half_rn(v[q]);
                hi[q] = __half2float(h);
                lo[q] = v[q] - hi[q];
            }
            uint4 w;
            w.x = pack_h2(hi[0], hi[1]);   // Bh reg0
            w.y = pack_h2(hi[2], hi[3]);   // Bh reg1
            w.z = pack_h2(lo[0], lo[1]);   // Bl reg0
            w.w = pack_h2(lo[2], lo[3]);   // Bl reg1
            if (!isL1) g_WfragL0[(kt * 32 + nt) * 32 + lane] = w;
            else       g_WfragL1[(kt * 64 + nt) * 32 + lane] = w;
        } else if (idx < T0 + T1 + 256) {
            int n = idx - (T0 + T1);
            int row = (n & 3) * H1 + (n >> 2);
            g_b0i[n] = b_ih0[row] + b_hh0[row];
        } else {
            int n = idx - (T0 + T1 + 256);
            int row = (n & 3) * H2 + (n >> 2);
            g_b1i[n] = b_ih1[row] + b_hh1[row];
        }
    }
}

// ---------------------------------------------------------------------------
// Main kernel: BT=32/block, 8 warps = ng 0..7, each warp M=32 (2 A-frags).
// MMA issue order: per kt, all Bh MMAs for 4 j x 2 frags (8 independent)
// before the matching Bl batch -> dependent MMAs 8 issues apart.
// Activations via HW tanh.approx (sigm = 0.5*tanh(x/2)+0.5).
// Phases: A1 = L0 GEMM + L0 EW; A2 = L1 h1-part (kt4..11); barrier;
//         B = L1 h0-part (kt0..3) + x(t+1) prefetch + L1 EW.
// ---------------------------------------------------------------------------
__global__ __launch_bounds__(NTH, 2) void lstm_mma(
    const float* __restrict__ xin,
    const float* __restrict__ Wd1, const float* __restrict__ bd1,
    const float* __restrict__ Wd2, const float* __restrict__ bd2,
    float* __restrict__ out)
{
    extern __shared__ unsigned char smraw[];
    __half* As   = (__half*)smraw;                                 // 32*424 fp16
    float* bias0 = (float*)(smraw + (size_t)BT * ASTRIDE * 2);     // 256
    float* bias1 = bias0 + 256;                                    // 512
    float* csm   = bias1 + 512;                                    // 24*256

    const int tid  = threadIdx.x;
    const int wid  = tid >> 5, lane = tid & 31;
    const int ng   = wid;                // 0..7 n-group
    const int grp  = lane >> 2;          // 0..7
    const int qc   = lane & 3;           // 0..3
    const int par  = lane & 1;
    const int ebase = blockIdx.x * BT;

    // init smem
    for (int i = tid; i < 256; i += NTH) bias0[i] = g_b0i[i];
    for (int i = tid; i < 512; i += NTH) bias1[i] = g_b1i[i];
    for (int i = tid; i < 24 * 256; i += NTH) csm[i] = 0.0f;
    for (int i = tid; i < BT * ASTRIDE; i += NTH)
        ((unsigned short*)As)[i] = 0;    // +0.0 fp16
    __syncthreads();

    // prologue: stage x(t=0) into x parity 0
    #pragma unroll
    for (int i = 0; i < 2; i++) {
        int idx = tid + i * NTH;
        int r = idx >> 4, c = idx & 15;
        float v = (c < F_IN) ? xin[((size_t)(ebase + r) * T_STEPS + 0) * F_IN + c] : 0.0f;
        As[r * ASTRIDE + XB + c] = __float2half_rn(v);
    }

    for (int t = 0; t < T_STEPS; t++) {
        const int xr0 = XB  + (t & 1) * 16;          // x(t)
        const int xw0 = XB  + ((t + 1) & 1) * 16;    // x(t+1) staging
        const int h0r = H0B + (t & 1) * 64;
        const int h0w = H0B + ((t + 1) & 1) * 64;
        const int h1r = H1B + (t & 1) * 128;
        const int h1w = H1B + ((t + 1) & 1) * 128;

        __syncthreads();   // x(t), h0(t), h1(t) visible

        // ========== Phase A1: L0 GEMM (K=80 = x(16) || h0_old(64)) ==========
        {
            float d0[8][4];   // [j*2+frag]
            #pragma unroll
            for (int j = 0; j < 4; j++) {
                float2 b = *(const float2*)&bias0[(ng * 4 + j) * 8 + qc * 2];
                d0[j*2+0][0] = b.x; d0[j*2+0][1] = b.y; d0[j*2+0][2] = b.x; d0[j*2+0][3] = b.y;
                d0[j*2+1][0] = b.x; d0[j*2+1][1] = b.y; d0[j*2+1][2] = b.x; d0[j*2+1][3] = b.y;
            }
            #pragma unroll
            for (int kt = 0; kt < 5; kt++) {
                int colbase = (kt == 0) ? (xr0 + qc * 2) : (h0r + (kt - 1) * 16 + qc * 2);
                unsigned a0[4], a1[4];
                ldA(a0, As, grp, colbase);        // frag0: rows 0..15
                ldA(a1, As, 16 + grp, colbase);   // frag1: rows 16..31
                uint4 w4[4];
                #pragma unroll
                for (int j = 0; j < 4; j++)
                    w4[j] = g_WfragL0[(kt * 32 + ng * 4 + j) * 32 + lane];
                #pragma unroll
                for (int j = 0; j < 4; j++) mma16816(d0[j*2+0], a0, w4[j].x, w4[j].y);
                #pragma unroll
                for (int j = 0; j < 4; j++) mma16816(d0[j*2+1], a1, w4[j].x, w4[j].y);
                #pragma unroll
                for (int j = 0; j < 4; j++) mma16816(d0[j*2+0], a0, w4[j].z, w4[j].w);
                #pragma unroll
                for (int j = 0; j < 4; j++) mma16816(d0[j*2+1], a1, w4[j].z, w4[j].w);
            }

            // ---- L0 elementwise -> h0[write parity] (d0 dies here) ----
            #pragma unroll
            for (int jf = 0; jf < 8; jf++) {
                int j = jf >> 1, f = jf & 1;
                float s0 = par ? d0[jf][0] : d0[jf][2];
                float s1 = par ? d0[jf][1] : d0[jf][3];
                float v0 = __shfl_xor_sync(0xffffffffu, s0, 1);
                float v1 = __shfl_xor_sync(0xffffffffu, s1, 1);
                float zi, zf, zg, zo;
                if (par == 0) { zi = d0[jf][0]; zf = d0[jf][1]; zg = v0; zo = v1; }
                else          { zi = v0; zf = v1; zg = d0[jf][2]; zo = d0[jf][3]; }
                float c = csm[jf * 256 + tid];
                c = fmaf(sigm(zf), c, sigm(zi) * tanh_hw(zg));
                csm[jf * 256 + tid] = c;
                float h = sigm(zo) * tanh_hw(c);
                int u  = (ng * 4 + j) * 2 + (qc >> 1);
                int rr = f * 16 + grp + (par ? 8 : 0);
                As[rr * ASTRIDE + h0w + u] = __float2half_rn(h);
            }
        }

        // ========== Phase A2: L1 h1-recurrent part (kt 4..11) ==========
        float d1[16][4];   // [j*2+frag]
        #pragma unroll
        for (int j = 0; j < 8; j++) {
            float2 b = *(const float2*)&bias1[(ng * 8 + j) * 8 + qc * 2];
            d1[j*2+0][0] = b.x; d1[j*2+0][1] = b.y; d1[j*2+0][2] = b.x; d1[j*2+0][3] = b.y;
            d1[j*2+1][0] = b.x; d1[j*2+1][1] = b.y; d1[j*2+1][2] = b.x; d1[j*2+1][3] = b.y;
        }
        #pragma unroll
        for (int kt = 4; kt < 12; kt++) {          // h1_old part (independent of h0_new)
            int colbase = h1r + (kt - 4) * 16 + qc * 2;
            unsigned a0[4], a1[4];
            ldA(a0, As, grp, colbase);
            ldA(a1, As, 16 + grp, colbase);
            #pragma unroll
            for (int jj = 0; jj < 8; jj += 4) {
                uint4 w4[4];
                #pragma unroll
                for (int j = 0; j < 4; j++)
                    w4[j] = g_WfragL1[(kt * 64 + ng * 8 + jj + j) * 32 + lane];
                #pragma unroll
                for (int j = 0; j < 4; j++) mma16816(d1[(jj+j)*2+0], a0, w4[j].x, w4[j].y);
                #pragma unroll
                for (int j = 0; j < 4; j++) mma16816(d1[(jj+j)*2+1], a1, w4[j].x, w4[j].y);
                #pragma unroll
                for (int j = 0; j < 4; j++) mma16816(d1[(jj+j)*2+0], a0, w4[j].z, w4[j].w);
                #pragma unroll
                for (int j = 0; j < 4; j++) mma16816(d1[(jj+j)*2+1], a1, w4[j].z, w4[j].w);
            }
        }
        __syncthreads();   // h0[new] complete block-wide

        // ========== Phase B: L1 h0-part (kt 0..3) + x(t+1) stage + L1 EW ====
        float xv[2];
        if (t + 1 < T_STEPS) {
            #pragma unroll
            for (int i = 0; i < 2; i++) {
                int idx = tid + i * NTH;
                int r = idx >> 4, c = idx & 15;
                xv[i] = (c < F_IN)
                    ? xin[((size_t)(ebase + r) * T_STEPS + (t + 1)) * F_IN + c] : 0.0f;
            }
        }

        #pragma unroll
        for (int kt = 0; kt < 4; kt++) {           // h0_new part
            int colbase = h0w + kt * 16 + qc * 2;
            unsigned a0[4], a1[4];
            ldA(a0, As, grp, colbase);
            ldA(a1, As, 16 + grp, colbase);
            #pragma unroll
            for (int jj = 0; jj < 8; jj += 4) {
                uint4 w4[4];
                #pragma unroll
                for (int j = 0; j < 4; j++)
                    w4[j] = g_WfragL1[(kt * 64 + ng * 8 + jj + j) * 32 + lane];
                #pragma unroll
                for (int j = 0; j < 4; j++) mma16816(d1[(jj+j)*2+0], a0, w4[j].x, w4[j].y);
                #pragma unroll
                for (int j = 0; j < 4; j++) mma16816(d1[(jj+j)*2+1], a1, w4[j].x, w4[j].y);
                #pragma unroll
                for (int j = 0; j < 4; j++) mma16816(d1[(jj+j)*2+0], a0, w4[j].z, w4[j].w);
                #pragma unroll
                for (int j = 0; j < 4; j++) mma16816(d1[(jj+j)*2+1], a1, w4[j].z, w4[j].w);
            }
        }

        if (t + 1 < T_STEPS) {
            #pragma unroll
            for (int i = 0; i < 2; i++) {
                int idx = tid + i * NTH;
                int r = idx >> 4, c = idx & 15;
                As[r * ASTRIDE + xw0 + c] = __float2half_rn(xv[i]);
            }
        }

        // ---- L1 elementwise -> h1[write parity] (next step's barrier covers) ----
        #pragma unroll
        for (int jf = 0; jf < 16; jf++) {
            int j = jf >> 1, f = jf & 1;
            float s0 = par ? d1[jf][0] : d1[jf][2];
            float s1 = par ? d1[jf][1] : d1[jf][3];
            float v0 = __shfl_xor_sync(0xffffffffu, s0, 1);
            float v1 = __shfl_xor_sync(0xffffffffu, s1, 1);
            float zi, zf, zg, zo;
            if (par == 0) { zi = d1[jf][0]; zf = d1[jf][1]; zg = v0; zo = v1; }
            else          { zi = v0; zf = v1; zg = d1[jf][2]; zo = d1[jf][3]; }
            float c = csm[(8 + jf) * 256 + tid];
            c = fmaf(sigm(zf), c, sigm(zi) * tanh_hw(zg));
            csm[(8 + jf) * 256 + tid] = c;
            float h = sigm(zo) * tanh_hw(c);
            int u  = (ng * 8 + j) * 2 + (qc >> 1);
            int rr = f * 16 + grp + (par ? 8 : 0);
            As[rr * ASTRIDE + h1w + u] = __float2half_rn(h);
        }
    }
    __syncthreads();   // final h1 (parity 0 at H1B) visible block-wide

    // ================= Dense head =================
    {
        int e = tid >> 3, q = tid & 7;      // 32 elems x 8 partials
        float s = 0.0f;
        for (int m = q * 8; m < q * 8 + 8; m++) {
            float dsum = bd1[m];
            #pragma unroll 4
            for (int jj = 0; jj < H2; jj++) {
                float hv = __half2float(As[e * ASTRIDE + H1B + jj]);
                dsum = fmaf(Wd1[m * H2 + jj], hv, dsum);
            }
            s = fmaf(Wd2[m], dsum, s);
        }
        csm[tid] = s;
        __syncthreads();
        if (q == 0) {
            float r = 0.0f;
            #pragma unroll
            for (int k = 0; k < 8; k++) r += csm[e * 8 + k];
            out[ebase + e] = r + bd2[0];
        }
    }
}

// ---------------------------------------------------------------------------
// Launch
// ---------------------------------------------------------------------------
extern "C" void kernel_launch(void* const* d_in, const int* in_sizes, int n_in,
                              void* d_out, int out_size)
{
    (void)in_sizes; (void)n_in; (void)out_size;
    const float* input_seq = (const float*)d_in[0];
    const float* W_ih0 = (const float*)d_in[1];
    const float* W_hh0 = (const float*)d_in[2];
    const float* b_ih0 = (const float*)d_in[3];
    const float* b_hh0 = (const float*)d_in[4];
    const float* W_ih1 = (const float*)d_in[5];
    const float* W_hh1 = (const float*)d_in[6];
    const float* b_ih1 = (const float*)d_in[7];
    const float* b_hh1 = (const float*)d_in[8];
    const float* W_d1  = (const float*)d_in[9];
    const float* b_d1  = (const float*)d_in[10];
    const float* W_d2  = (const float*)d_in[11];
    const float* b_d2  = (const float*)d_in[12];

    const size_t smem_bytes = (size_t)BT * ASTRIDE * 2          // A plane (27136)
                            + (256 + 512) * sizeof(float)       // biases  (3072)
                            + 24 * 256 * sizeof(float);         // c state (24576)
    cudaFuncSetAttribute(lstm_mma, cudaFuncAttributeMaxDynamicSharedMemorySize, (int)smem_bytes);

    repack<<<128, 256>>>(W_ih0, W_hh0, b_ih0, b_hh0, W_ih1, W_hh1, b_ih1, b_hh1);
    lstm_mma<<<GRID, NTH, smem_bytes>>>(input_seq, W_d1, b_d1, W_d2, b_d2, (float*)d_out);
}

// round 17
// speedup vs baseline: 9.4134x; 1.5510x over previous
#include <cuda_runtime.h>
#include <cuda_fp16.h>
#include <cstddef>

// Problem constants
#define B_TOT   16384
#define T_STEPS 128
#define F_IN    12
#define H1      64
#define H2      128
#define BT      32
#define NTH     256
#define GRID    (B_TOT / BT)   // 512

// A-buffer geometry (single fp16 plane in smem), stride 424:
// cols [0,16)=x par0, [16,32)=x par1, [32,96)=h0 par0, [96,160)=h0 par1,
//      [160,288)=h1 par0, [288,416)=h1 par1
#define XB      0
#define H0B     32
#define H1B     160
#define ASTRIDE 424

// ---------------------------------------------------------------------------
// Device-global scratch (weights only, single fp16 term; ~240KB)
// ---------------------------------------------------------------------------
__device__ uint2 g_WfragL0h[5 * 32 * 32];   // [kt][nt][lane] -> (bh0,bh1) fp16x2
__device__ uint2 g_WfragL1h[12 * 64 * 32];
__device__ float g_b0i[256];                // gate-pair-interleaved biases
__device__ float g_b1i[512];

// ---------------------------------------------------------------------------
// Helpers
// ---------------------------------------------------------------------------
__device__ __forceinline__ unsigned pack_h2(float a, float b) {
    __half2 t = __floats2half2_rn(a, b);
    unsigned r; memcpy(&r, &t, 4); return r;
}
// HW tanh (MUFU.TANH, sm_75+): 1 MUFU op, rel err ~2^-11
__device__ __forceinline__ float tanh_hw(float x) {
    float r; asm("tanh.approx.f32 %0, %1;" : "=f"(r) : "f"(x)); return r;
}
__device__ __forceinline__ float sigm(float x) {
    return fmaf(0.5f, tanh_hw(0.5f * x), 0.5f);
}

__device__ __forceinline__ void mma16816(float* d, const unsigned* a, unsigned b0, unsigned b1) {
    asm volatile(
        "mma.sync.aligned.m16n8k16.row.col.f32.f16.f16.f32 "
        "{%0,%1,%2,%3}, {%4,%5,%6,%7}, {%8,%9}, {%0,%1,%2,%3};\n"
        : "+f"(d[0]), "+f"(d[1]), "+f"(d[2]), "+f"(d[3])
        : "r"(a[0]), "r"(a[1]), "r"(a[2]), "r"(a[3]), "r"(b0), "r"(b1));
}

// A fragment (m16k16, row-major): a0=[r][c..c+1] a1=[r+8][c..] a2=[r][c+8..] a3=[r+8][c+8..]
__device__ __forceinline__ void ldA(unsigned* a, const __half* plane, int row0, int colbase) {
    a[0] = *(const unsigned*)&plane[row0 * ASTRIDE + colbase];
    a[1] = *(const unsigned*)&plane[(row0 + 8) * ASTRIDE + colbase];
    a[2] = *(const unsigned*)&plane[row0 * ASTRIDE + colbase + 8];
    a[3] = *(const unsigned*)&plane[(row0 + 8) * ASTRIDE + colbase + 8];
}

// Gate-pair interleave: col n -> unit/gate such that one thread's 2 cols in
// tile 2p hold (i,f) of a unit and its 2 cols in tile 2p+1 hold (g,o).
// p = n>>4, c = n&15: unit = p*4 + ((c&7)>>1), gate = ((c>>3)<<1) | (c&1)
__device__ __forceinline__ void col_to_ug(int n, int& unit, int& gate) {
    int p = n >> 4, c = n & 15;
    unit = p * 4 + ((c & 7) >> 1);
    gate = ((c >> 3) << 1) | (c & 1);
}

// ---------------------------------------------------------------------------
// Repack: weights -> mma B-fragment order (single fp16 term), gate-pair interleave
// B frag (k16 x n8, "col"): lane t, reg r, half h -> k = (t%4)*2 + r*8 + h, n = t/4
// ---------------------------------------------------------------------------
__global__ void repack(const float* __restrict__ W_ih0, const float* __restrict__ W_hh0,
                       const float* __restrict__ b_ih0, const float* __restrict__ b_hh0,
                       const float* __restrict__ W_ih1, const float* __restrict__ W_hh1,
                       const float* __restrict__ b_ih1, const float* __restrict__ b_hh1)
{
    const int T0 = 5 * 32 * 32, T1 = 12 * 64 * 32;
    for (int idx = blockIdx.x * blockDim.x + threadIdx.x;
         idx < T0 + T1 + 256 + 512; idx += gridDim.x * blockDim.x) {
        if (idx < T0 + T1) {
            int lidx = idx, isL1 = 0;
            if (lidx >= T0) { lidx -= T0; isL1 = 1; }
            int lane = lidx & 31;
            int ntcnt = isL1 ? 64 : 32;
            int nt = (lidx >> 5) % ntcnt;
            int kt = (lidx >> 5) / ntcnt;
            int n = nt * 8 + (lane >> 2);
            int unit, gate;
            col_to_ug(n, unit, gate);
            float v[4];
            #pragma unroll
            for (int q = 0; q < 4; q++) {
                int k = kt * 16 + (lane & 3) * 2 + (q >> 1) * 8 + (q & 1);
                float val;
                if (!isL1) {
                    int row = gate * H1 + unit;
                    if (k < 16) val = (k < F_IN) ? W_ih0[row * F_IN + k] : 0.0f;
                    else        val = W_hh0[row * H1 + (k - 16)];
                } else {
                    int row = gate * H2 + unit;
                    if (k < 64) val = W_ih1[row * H1 + k];
                    else        val = W_hh1[row * H2 + (k - 64)];
                }
                v[q] = val;
            }
            uint2 w;
            w.x = pack_h2(v[0], v[1]);
            w.y = pack_h2(v[2], v[3]);
            if (!isL1) g_WfragL0h[(kt * 32 + nt) * 32 + lane] = w;
            else       g_WfragL1h[(kt * 64 + nt) * 32 + lane] = w;
        } else if (idx < T0 + T1 + 256) {
            int n = idx - (T0 + T1);
            int unit, gate;
            col_to_ug(n, unit, gate);
            int row = gate * H1 + unit;
            g_b0i[n] = b_ih0[row] + b_hh0[row];
        } else {
            int n = idx - (T0 + T1 + 256);
            int unit, gate;
            col_to_ug(n, unit, gate);
            int row = gate * H2 + unit;
            g_b1i[n] = b_ih1[row] + b_hh1[row];
        }
    }
}

// ---------------------------------------------------------------------------
// Main kernel: BT=32/block, 8 warps = ng 0..7, each warp M=32 (2 A-frags).
// Single-term fp16 MMA; gate-pair interleave -> shfl-free elementwise
// (each thread holds i,f,g,o of its unit in d[2jp]/d[2jp+1] registers).
// Phases: A1 = L0 GEMM + L0 EW; A2 = L1 h1-part (kt4..11); barrier;
//         B = L1 h0-part (kt0..3) + x(t+1) prefetch + L1 EW.
// ---------------------------------------------------------------------------
__global__ __launch_bounds__(NTH, 2) void lstm_mma(
    const float* __restrict__ xin,
    const float* __restrict__ Wd1, const float* __restrict__ bd1,
    const float* __restrict__ Wd2, const float* __restrict__ bd2,
    float* __restrict__ out)
{
    extern __shared__ unsigned char smraw[];
    __half* As   = (__half*)smraw;                                 // 32*424 fp16
    float* bias0 = (float*)(smraw + (size_t)BT * ASTRIDE * 2);     // 256
    float* bias1 = bias0 + 256;                                    // 512
    float* csm   = bias1 + 512;                                    // 24*256

    const int tid  = threadIdx.x;
    const int wid  = tid >> 5, lane = tid & 31;
    const int ng   = wid;                // 0..7 n-group
    const int grp  = lane >> 2;          // 0..7
    const int qc   = lane & 3;           // 0..3
    const int ebase = blockIdx.x * BT;

    // init smem
    for (int i = tid; i < 256; i += NTH) bias0[i] = g_b0i[i];
    for (int i = tid; i < 512; i += NTH) bias1[i] = g_b1i[i];
    for (int i = tid; i < 24 * 256; i += NTH) csm[i] = 0.0f;
    for (int i = tid; i < BT * ASTRIDE; i += NTH)
        ((unsigned short*)As)[i] = 0;    // +0.0 fp16
    __syncthreads();

    // prologue: stage x(t=0) into x parity 0
    #pragma unroll
    for (int i = 0; i < 2; i++) {
        int idx = tid + i * NTH;
        int r = idx >> 4, c = idx & 15;
        float v = (c < F_IN) ? xin[((size_t)(ebase + r) * T_STEPS + 0) * F_IN + c] : 0.0f;
        As[r * ASTRIDE + XB + c] = __float2half_rn(v);
    }

    for (int t = 0; t < T_STEPS; t++) {
        const int xr0 = XB  + (t & 1) * 16;          // x(t)
        const int xw0 = XB  + ((t + 1) & 1) * 16;    // x(t+1) staging
        const int h0r = H0B + (t & 1) * 64;
        const int h0w = H0B + ((t + 1) & 1) * 64;
        const int h1r = H1B + (t & 1) * 128;
        const int h1w = H1B + ((t + 1) & 1) * 128;

        __syncthreads();   // x(t), h0(t), h1(t) visible

        // ========== Phase A1: L0 GEMM (K=80 = x(16) || h0_old(64)) ==========
        {
            float d0[8][4];   // [j*2+frag]
            #pragma unroll
            for (int j = 0; j < 4; j++) {
                float2 b = *(const float2*)&bias0[(ng * 4 + j) * 8 + qc * 2];
                d0[j*2+0][0] = b.x; d0[j*2+0][1] = b.y; d0[j*2+0][2] = b.x; d0[j*2+0][3] = b.y;
                d0[j*2+1][0] = b.x; d0[j*2+1][1] = b.y; d0[j*2+1][2] = b.x; d0[j*2+1][3] = b.y;
            }
            #pragma unroll
            for (int kt = 0; kt < 5; kt++) {
                int colbase = (kt == 0) ? (xr0 + qc * 2) : (h0r + (kt - 1) * 16 + qc * 2);
                unsigned a0[4], a1[4];
                ldA(a0, As, grp, colbase);        // frag0: rows 0..15
                ldA(a1, As, 16 + grp, colbase);   // frag1: rows 16..31
                uint2 w2[4];
                #pragma unroll
                for (int j = 0; j < 4; j++)
                    w2[j] = g_WfragL0h[(kt * 32 + ng * 4 + j) * 32 + lane];
                #pragma unroll
                for (int j = 0; j < 4; j++) mma16816(d0[j*2+0], a0, w2[j].x, w2[j].y);
                #pragma unroll
                for (int j = 0; j < 4; j++) mma16816(d0[j*2+1], a1, w2[j].x, w2[j].y);
            }

            // ---- L0 elementwise (shfl-free) -> h0[write parity] ----
            #pragma unroll
            for (int jp = 0; jp < 2; jp++) {
                #pragma unroll
                for (int f = 0; f < 2; f++) {
                    #pragma unroll
                    for (int rh = 0; rh < 2; rh++) {
                        float zi = d0[(2*jp+0)*2+f][rh*2+0];
                        float zf = d0[(2*jp+0)*2+f][rh*2+1];
                        float zg = d0[(2*jp+1)*2+f][rh*2+0];
                        float zo = d0[(2*jp+1)*2+f][rh*2+1];
                        int slot = jp*4 + f*2 + rh;
                        float c = csm[slot * 256 + tid];
                        c = fmaf(sigm(zf), c, sigm(zi) * tanh_hw(zg));
                        csm[slot * 256 + tid] = c;
                        float h = sigm(zo) * tanh_hw(c);
                        int unit = (ng * 2 + jp) * 4 + qc;
                        int rr = f * 16 + grp + rh * 8;
                        As[rr * ASTRIDE + h0w + unit] = __float2half_rn(h);
                    }
                }
            }
        }

        // ========== Phase A2: L1 h1-recurrent part (kt 4..11) ==========
        float d1[16][4];   // [j*2+frag]
        #pragma unroll
        for (int j = 0; j < 8; j++) {
            float2 b = *(const float2*)&bias1[(ng * 8 + j) * 8 + qc * 2];
            d1[j*2+0][0] = b.x; d1[j*2+0][1] = b.y; d1[j*2+0][2] = b.x; d1[j*2+0][3] = b.y;
            d1[j*2+1][0] = b.x; d1[j*2+1][1] = b.y; d1[j*2+1][2] = b.x; d1[j*2+1][3] = b.y;
        }
        #pragma unroll
        for (int kt = 4; kt < 12; kt++) {          // h1_old part (independent of h0_new)
            int colbase = h1r + (kt - 4) * 16 + qc * 2;
            unsigned a0[4], a1[4];
            ldA(a0, As, grp, colbase);
            ldA(a1, As, 16 + grp, colbase);
            #pragma unroll
            for (int jj = 0; jj < 8; jj += 4) {
                uint2 w2[4];
                #pragma unroll
                for (int j = 0; j < 4; j++)
                    w2[j] = g_WfragL1h[(kt * 64 + ng * 8 + jj + j) * 32 + lane];
                #pragma unroll
                for (int j = 0; j < 4; j++) mma16816(d1[(jj+j)*2+0], a0, w2[j].x, w2[j].y);
                #pragma unroll
                for (int j = 0; j < 4; j++) mma16816(d1[(jj+j)*2+1], a1, w2[j].x, w2[j].y);
            }
        }
        __syncthreads();   // h0[new] complete block-wide

        // ========== Phase B: L1 h0-part (kt 0..3) + x(t+1) stage + L1 EW ====
        float xv[2];
        if (t + 1 < T_STEPS) {
            #pragma unroll
            for (int i = 0; i < 2; i++) {
                int idx = tid + i * NTH;
                int r = idx >> 4, c = idx & 15;
                xv[i] = (c < F_IN)
                    ? xin[((size_t)(ebase + r) * T_STEPS + (t + 1)) * F_IN + c] : 0.0f;
            }
        }

        #pragma unroll
        for (int kt = 0; kt < 4; kt++) {           // h0_new part
            int colbase = h0w + kt * 16 + qc * 2;
            unsigned a0[4], a1[4];
            ldA(a0, As, grp, colbase);
            ldA(a1, As, 16 + grp, colbase);
            #pragma unroll
            for (int jj = 0; jj < 8; jj += 4) {
                uint2 w2[4];
                #pragma unroll
                for (int j = 0; j < 4; j++)
                    w2[j] = g_WfragL1h[(kt * 64 + ng * 8 + jj + j) * 32 + lane];
                #pragma unroll
                for (int j = 0; j < 4; j++) mma16816(d1[(jj+j)*2+0], a0, w2[j].x, w2[j].y);
                #pragma unroll
                for (int j = 0; j < 4; j++) mma16816(d1[(jj+j)*2+1], a1, w2[j].x, w2[j].y);
            }
        }

        if (t + 1 < T_STEPS) {
            #pragma unroll
            for (int i = 0; i < 2; i++) {
                int idx = tid + i * NTH;
                int r = idx >> 4, c = idx & 15;
                As[r * ASTRIDE + xw0 + c] = __float2half_rn(xv[i]);
            }
        }

        // ---- L1 elementwise (shfl-free) -> h1[write parity] ----
        #pragma unroll
        for (int jp = 0; jp < 4; jp++) {
            #pragma unroll
            for (int f = 0; f < 2; f++) {
                #pragma unroll
                for (int rh = 0; rh < 2; rh++) {
                    float zi = d1[(2*jp+0)*2+f][rh*2+0];
                    float zf = d1[(2*jp+0)*2+f][rh*2+1];
                    float zg = d1[(2*jp+1)*2+f][rh*2+0];
                    float zo = d1[(2*jp+1)*2+f][rh*2+1];
                    int slot = 8 + jp*4 + f*2 + rh;
                    float c = csm[slot * 256 + tid];
                    c = fmaf(sigm(zf), c, sigm(zi) * tanh_hw(zg));
                    csm[slot * 256 + tid] = c;
                    float h = sigm(zo) * tanh_hw(c);
                    int unit = (ng * 4 + jp) * 4 + qc;
                    int rr = f * 16 + grp + rh * 8;
                    As[rr * ASTRIDE + h1w + unit] = __float2half_rn(h);
                }
            }
        }
    }
    __syncthreads();   // final h1 (parity 0 at H1B) visible block-wide

    // ================= Dense head =================
    {
        int e = tid >> 3, q = tid & 7;      // 32 elems x 8 partials
        float s = 0.0f;
        for (int m = q * 8; m < q * 8 + 8; m++) {
            float dsum = bd1[m];
            #pragma unroll 4
            for (int jj = 0; jj < H2; jj++) {
                float hv = __half2float(As[e * ASTRIDE + H1B + jj]);
                dsum = fmaf(Wd1[m * H2 + jj], hv, dsum);
            }
            s = fmaf(Wd2[m], dsum, s);
        }
        csm[tid] = s;
        __syncthreads();
        if (q == 0) {
            float r = 0.0f;
            #pragma unroll
            for (int k = 0; k < 8; k++) r += csm[e * 8 + k];
            out[ebase + e] = r + bd2[0];
        }
    }
}

// ---------------------------------------------------------------------------
// Launch
// ---------------------------------------------------------------------------
extern "C" void kernel_launch(void* const* d_in, const int* in_sizes, int n_in,
                              void* d_out, int out_size)
{
    (void)in_sizes; (void)n_in; (void)out_size;
    const float* input_seq = (const float*)d_in[0];
    const float* W_ih0 = (const float*)d_in[1];
    const float* W_hh0 = (const float*)d_in[2];
    const float* b_ih0 = (const float*)d_in[3];
    const float* b_hh0 = (const float*)d_in[4];
    const float* W_ih1 = (const float*)d_in[5];
    const float* W_hh1 = (const float*)d_in[6];
    const float* b_ih1 = (const float*)d_in[7];
    const float* b_hh1 = (const float*)d_in[8];
    const float* W_d1  = (const float*)d_in[9];
    const float* b_d1  = (const float*)d_in[10];
    const float* W_d2  = (const float*)d_in[11];
    const float* b_d2  = (const float*)d_in[12];

    const size_t smem_bytes = (size_t)BT * ASTRIDE * 2          // A plane (27136)
                            + (256 + 512) * sizeof(float)       // biases  (3072)
                            + 24 * 256 * sizeof(float);         // c state (24576)
    cudaFuncSetAttribute(lstm_mma, cudaFuncAttributeMaxDynamicSharedMemorySize, (int)smem_bytes);

    repack<<<128, 256>>>(W_ih0, W_hh0, b_ih0, b_hh0, W_ih1, W_hh1, b_ih1, b_hh1);
    lstm_mma<<<GRID, NTH, smem_bytes>>>(input_seq, W_d1, b_d1, W_d2, b_d2, (float*)d_out);
}